// round 1
// baseline (speedup 1.0000x reference)
#include <cuda_runtime.h>
#include <math.h>
#include <stddef.h>

// ---------------- problem constants ----------------
#define BB 2
#define LL 2048
#define DM 1024
#define DIN 2048
#define NHH 32
#define HD 64
#define DS 64
#define DCONVK 4
#define CONV_DIM (DIN + 2*DS)        // 2176
#define DPROJ (2*DIN + 2*DS + NHH)   // 4256
#define MLPI 4096
#define MTOK (BB*LL)                 // 4096
#define EPSV 1e-5f

// ---------------- scratch (device globals; no allocation allowed) ----------------
__device__ float g_zx [MTOK*(size_t)DPROJ];    // in-proj output
__device__ float g_xbc[MTOK*(size_t)CONV_DIM]; // conv+silu output
__device__ float g_dt [MTOK*NHH];
__device__ float g_dA [MTOK*NHH];
__device__ float g_y  [MTOK*(size_t)DIN];      // scan output (+D*xs)
__device__ float g_yn [MTOK*(size_t)DIN];      // gated+rmsnormed
__device__ float g_h  [MTOK*(size_t)DM];       // residual stream
__device__ float g_hn [MTOK*(size_t)DM];       // rmsnorm(h)
__device__ float g_act[MTOK*(size_t)MLPI];     // mlp hidden

// ---------------- generic fp32 tiled GEMM: C = epi(A @ B) ----------------
// BM=BN=64, BK=16, 256 threads, 4x4 per thread.
template<bool SILU>
__global__ void gemm_k(const float* __restrict__ A, const float* __restrict__ Bw,
                       const float* __restrict__ bias, const float* __restrict__ res,
                       float* __restrict__ C, int M, int N, int K)
{
    __shared__ float As[16][68];
    __shared__ float Bs[16][68];
    const int tx = threadIdx.x & 15;
    const int ty = threadIdx.x >> 4;
    const int row0 = blockIdx.y * 64;
    const int col0 = blockIdx.x * 64;

    float acc[4][4] = {};

    const int la_r = threadIdx.x >> 2;        // 0..63
    const int la_k = (threadIdx.x & 3) * 4;   // 0..12
    const int lb_k = threadIdx.x >> 4;        // 0..15
    const int lb_c = (threadIdx.x & 15) * 4;  // 0..60

    for (int kt = 0; kt < K; kt += 16) {
        // A tile (M divisible by 64, K by 16 in all our calls)
        float4 av = *(const float4*)(A + (size_t)(row0 + la_r) * K + kt + la_k);
        As[la_k+0][la_r] = av.x; As[la_k+1][la_r] = av.y;
        As[la_k+2][la_r] = av.z; As[la_k+3][la_r] = av.w;
        // B tile with N-edge guard
        int bc = col0 + lb_c;
        const float* brow = Bw + (size_t)(kt + lb_k) * N;
        float4 bv;
        if (bc + 3 < N) {
            bv = *(const float4*)(brow + bc);
        } else {
            bv.x = (bc+0 < N) ? brow[bc+0] : 0.f;
            bv.y = (bc+1 < N) ? brow[bc+1] : 0.f;
            bv.z = (bc+2 < N) ? brow[bc+2] : 0.f;
            bv.w = (bc+3 < N) ? brow[bc+3] : 0.f;
        }
        *(float4*)&Bs[lb_k][lb_c] = bv;
        __syncthreads();

        #pragma unroll
        for (int k = 0; k < 16; k++) {
            float a[4], b[4];
            #pragma unroll
            for (int i = 0; i < 4; i++) a[i] = As[k][ty*4 + i];
            #pragma unroll
            for (int j = 0; j < 4; j++) b[j] = Bs[k][tx*4 + j];
            #pragma unroll
            for (int i = 0; i < 4; i++)
                #pragma unroll
                for (int j = 0; j < 4; j++)
                    acc[i][j] = fmaf(a[i], b[j], acc[i][j]);
        }
        __syncthreads();
    }

    #pragma unroll
    for (int i = 0; i < 4; i++) {
        int r = row0 + ty*4 + i;
        #pragma unroll
        for (int j = 0; j < 4; j++) {
            int c = col0 + tx*4 + j;
            if (c < N) {
                float v = acc[i][j];
                if (bias) v += bias[c];
                if (SILU) v = v / (1.f + expf(-v));
                if (res)  v += res[(size_t)r * N + c];
                C[(size_t)r * N + c] = v;
            }
        }
    }
}

// ---------------- depthwise causal conv (k=4) + bias + silu ----------------
__global__ void conv_k(const float* __restrict__ conv_w, const float* __restrict__ conv_b)
{
    int idx = blockIdx.x * blockDim.x + threadIdx.x;
    if (idx >= MTOK * CONV_DIM) return;
    int c   = idx % CONV_DIM;
    int tok = idx / CONV_DIM;
    int t   = tok % LL;
    long long base = (long long)tok * DPROJ + DIN + c;
    float acc = conv_b[c];
    #pragma unroll
    for (int k = 0; k < DCONVK; k++) {
        int tt = t - (DCONVK - 1) + k;
        if (tt >= 0)
            acc = fmaf(g_zx[base + (long long)(k - (DCONVK - 1)) * DPROJ], conv_w[c*DCONVK + k], acc);
    }
    g_xbc[idx] = acc / (1.f + expf(-acc));
}

// ---------------- dt = softplus(dt_raw + bias), dA = exp(dt * -exp(A_log)) ----------------
__global__ void dt_k(const float* __restrict__ dt_bias, const float* __restrict__ A_log)
{
    int idx = blockIdx.x * blockDim.x + threadIdx.x;
    if (idx >= MTOK * NHH) return;
    int h   = idx % NHH;
    int tok = idx / NHH;
    float x = g_zx[(size_t)tok * DPROJ + DIN + CONV_DIM + h] + dt_bias[h];
    float dt = (x > 20.f) ? x : log1pf(expf(x));
    g_dt[idx] = dt;
    g_dA[idx] = expf(-expf(A_log[h]) * dt);
}

// ---------------- sequential selective scan: one block per (b, head) ----------------
// 512 threads; thread t owns p = t>>3, state slice n in [(t&7)*8, +8). State in registers.
__global__ void scan_k(const float* __restrict__ D_param)
{
    int b = blockIdx.x >> 5;
    int h = blockIdx.x & 31;
    int tid = threadIdx.x;
    int p  = tid >> 3;
    int n0 = (tid & 7) * 8;
    float hs[8] = {};
    float Dv = D_param[h];

    for (int t = 0; t < LL; t++) {
        int tok = b * LL + t;
        const float* xrow = g_xbc + (size_t)tok * CONV_DIM;
        float dA = g_dA[tok*NHH + h];
        float dt = g_dt[tok*NHH + h];
        float xp = xrow[h*HD + p];
        float dtx = dt * xp;
        float4 B1 = *(const float4*)(xrow + DIN + n0);
        float4 B2 = *(const float4*)(xrow + DIN + n0 + 4);
        float4 C1 = *(const float4*)(xrow + DIN + DS + n0);
        float4 C2 = *(const float4*)(xrow + DIN + DS + n0 + 4);
        float Bv[8] = {B1.x,B1.y,B1.z,B1.w,B2.x,B2.y,B2.z,B2.w};
        float Cv[8] = {C1.x,C1.y,C1.z,C1.w,C2.x,C2.y,C2.z,C2.w};
        float part = 0.f;
        #pragma unroll
        for (int i = 0; i < 8; i++) {
            hs[i] = fmaf(dA, hs[i], dtx * Bv[i]);
            part  = fmaf(hs[i], Cv[i], part);
        }
        part += __shfl_down_sync(0xffffffffu, part, 4);
        part += __shfl_down_sync(0xffffffffu, part, 2);
        part += __shfl_down_sync(0xffffffffu, part, 1);
        if ((tid & 7) == 0)
            g_y[(size_t)tok * DIN + h*HD + p] = part + Dv * xp;
    }
}

// ---------------- gated RMSNorm: yn = rmsnorm(y * silu(z)) * norm_w ----------------
__global__ void gatenorm_k(const float* __restrict__ norm_w)
{
    int tok = blockIdx.x;
    __shared__ float sv[DIN];
    __shared__ float red[256];
    const float* yrow = g_y  + (size_t)tok * DIN;
    const float* zrow = g_zx + (size_t)tok * DPROJ;
    float ss = 0.f;
    for (int c = threadIdx.x; c < DIN; c += 256) {
        float z = zrow[c];
        float v = yrow[c] * (z / (1.f + expf(-z)));
        sv[c] = v;
        ss += v * v;
    }
    red[threadIdx.x] = ss; __syncthreads();
    for (int s = 128; s > 0; s >>= 1) {
        if (threadIdx.x < s) red[threadIdx.x] += red[threadIdx.x + s];
        __syncthreads();
    }
    float scale = rsqrtf(red[0] / DIN + EPSV);
    for (int c = threadIdx.x; c < DIN; c += 256)
        g_yn[(size_t)tok * DIN + c] = sv[c] * scale * norm_w[c];
}

// ---------------- plain RMSNorm over DM ----------------
__global__ void rmsnorm_k(const float* __restrict__ x, const float* __restrict__ w,
                          float* __restrict__ out)
{
    int tok = blockIdx.x;
    __shared__ float sv[DM];
    __shared__ float red[256];
    const float* xr = x + (size_t)tok * DM;
    float ss = 0.f;
    for (int c = threadIdx.x; c < DM; c += 256) {
        float v = xr[c];
        sv[c] = v;
        ss += v * v;
    }
    red[threadIdx.x] = ss; __syncthreads();
    for (int s = 128; s > 0; s >>= 1) {
        if (threadIdx.x < s) red[threadIdx.x] += red[threadIdx.x + s];
        __syncthreads();
    }
    float scale = rsqrtf(red[0] / DM + EPSV);
    for (int c = threadIdx.x; c < DM; c += 256)
        out[(size_t)tok * DM + c] = sv[c] * scale * w[c];
}

// ---------------- launch ----------------
extern "C" void kernel_launch(void* const* d_in, const int* in_sizes, int n_in,
                              void* d_out, int out_size)
{
    const float* x        = (const float*)d_in[0];   // [4096,1024]
    const float* W_in     = (const float*)d_in[1];   // [1024,4256]
    const float* conv_w   = (const float*)d_in[2];   // [2176,4]
    const float* conv_b   = (const float*)d_in[3];   // [2176]
    const float* dt_bias  = (const float*)d_in[4];   // [32]
    const float* A_log    = (const float*)d_in[5];   // [32]
    const float* D_param  = (const float*)d_in[6];   // [32]
    const float* norm_w   = (const float*)d_in[7];   // [2048]
    const float* W_out    = (const float*)d_in[8];   // [2048,1024]
    const float* rms_w    = (const float*)d_in[9];   // [1024]
    const float* mlp_w1   = (const float*)d_in[10];  // [1024,4096]
    const float* mlp_b1   = (const float*)d_in[11];  // [4096]
    const float* mlp_w2   = (const float*)d_in[12];  // [4096,1024]
    const float* mlp_b2   = (const float*)d_in[13];  // [1024]
    float* out            = (float*)d_out;

    float *p_zx, *p_xbc_unused, *p_yn, *p_h, *p_hn, *p_act;
    cudaGetSymbolAddress((void**)&p_zx,  g_zx);
    cudaGetSymbolAddress((void**)&p_yn,  g_yn);
    cudaGetSymbolAddress((void**)&p_h,   g_h);
    cudaGetSymbolAddress((void**)&p_hn,  g_hn);
    cudaGetSymbolAddress((void**)&p_act, g_act);
    (void)p_xbc_unused; (void)in_sizes; (void)n_in; (void)out_size;

    dim3 blk(256);

    // 1. in-projection: zx = x @ W_in   [4096 x 4256]
    gemm_k<false><<<dim3((DPROJ+63)/64, MTOK/64), blk>>>(x, W_in, nullptr, nullptr,
                                                         p_zx, MTOK, DPROJ, DM);
    // 2. depthwise conv + silu
    conv_k<<<(MTOK*CONV_DIM + 255)/256, blk>>>(conv_w, conv_b);
    // 3. dt / dA
    dt_k<<<(MTOK*NHH + 255)/256, blk>>>(dt_bias, A_log);
    // 4. selective scan
    scan_k<<<BB*NHH, 512>>>(D_param);
    // 5. gate + rmsnorm
    gatenorm_k<<<MTOK, blk>>>(norm_w);
    // 6. out-projection + residual: h = x + yn @ W_out
    gemm_k<false><<<dim3(DM/64, MTOK/64), blk>>>(p_yn, W_out, nullptr, x,
                                                 p_h, MTOK, DM, DIN);
    // 7. hn = rmsnorm(h)
    rmsnorm_k<<<MTOK, blk>>>(p_h, rms_w, p_hn);
    // 8. mlp hidden: act = silu(hn @ mlp_w1 + b1)
    gemm_k<true><<<dim3(MLPI/64, MTOK/64), blk>>>(p_hn, mlp_w1, mlp_b1, nullptr,
                                                  p_act, MTOK, MLPI, DM);
    // 9. out = h + act @ mlp_w2 + b2
    gemm_k<false><<<dim3(DM/64, MTOK/64), blk>>>(p_act, mlp_w2, mlp_b2, p_h,
                                                 out, MTOK, DM, MLPI);
}

// round 3
// speedup vs baseline: 1.8324x; 1.8324x over previous
#include <cuda_runtime.h>
#include <cuda_bf16.h>
#include <math.h>
#include <stddef.h>
#include <stdint.h>

// ---------------- problem constants ----------------
#define BB 2
#define LL 2048
#define DM 1024
#define DIN 2048
#define NHH 32
#define HD 64
#define DS 64
#define DCONVK 4
#define CONV_DIM (DIN + 2*DS)        // 2176
#define DPROJ (2*DIN + 2*DS + NHH)   // 4256
#define DPROJ_PAD 4352               // multiple of 128
#define MLPI 4096
#define MTOK (BB*LL)                 // 4096
#define EPSV 1e-5f

// ---------------- scratch (device globals) ----------------
__device__ float g_zx [MTOK*(size_t)DPROJ];
__device__ float g_xbc[MTOK*(size_t)CONV_DIM];
__device__ float g_dt [MTOK*NHH];
__device__ float g_dA [MTOK*NHH];
__device__ float g_y  [MTOK*(size_t)DIN];
__device__ float g_h  [MTOK*(size_t)DM];

__device__ __nv_bfloat16 g_xs_h [MTOK*(size_t)DM],   g_xs_l [MTOK*(size_t)DM];
__device__ __nv_bfloat16 g_yn_h [MTOK*(size_t)DIN],  g_yn_l [MTOK*(size_t)DIN];
__device__ __nv_bfloat16 g_hn_h [MTOK*(size_t)DM],   g_hn_l [MTOK*(size_t)DM];
__device__ __nv_bfloat16 g_act_h[MTOK*(size_t)MLPI], g_act_l[MTOK*(size_t)MLPI];

__device__ __nv_bfloat16 g_win_h [DPROJ_PAD*(size_t)DM],  g_win_l [DPROJ_PAD*(size_t)DM];
__device__ __nv_bfloat16 g_wout_h[DM*(size_t)DIN],        g_wout_l[DM*(size_t)DIN];
__device__ __nv_bfloat16 g_w1_h  [MLPI*(size_t)DM],       g_w1_l  [MLPI*(size_t)DM];
__device__ __nv_bfloat16 g_w2_h  [DM*(size_t)MLPI],       g_w2_l  [DM*(size_t)MLPI];

// ---------------- small asm helpers (all baseline PTX, sm_80+) ----------------
__device__ __forceinline__ uint32_t smem_u32(const void* p) {
    uint32_t a;
    asm("{ .reg .u64 t; cvta.to.shared.u64 t, %1; cvt.u32.u64 %0, t; }" : "=r"(a) : "l"(p));
    return a;
}
__device__ __forceinline__ void cp_async16(uint32_t dst, const void* src) {
    asm volatile("cp.async.ca.shared.global [%0], [%1], 16;" :: "r"(dst), "l"(src) : "memory");
}
__device__ __forceinline__ void cp_commit() {
    asm volatile("cp.async.commit_group;" ::: "memory");
}
template<int N> __device__ __forceinline__ void cp_wait() {
    asm volatile("cp.async.wait_group %0;" :: "n"(N) : "memory");
}
__device__ __forceinline__ void ldsm4(uint32_t* r, uint32_t addr) {
    asm volatile("ldmatrix.sync.aligned.m8n8.x4.shared.b16 {%0,%1,%2,%3}, [%4];"
                 : "=r"(r[0]), "=r"(r[1]), "=r"(r[2]), "=r"(r[3]) : "r"(addr));
}
__device__ __forceinline__ void ldsm2(uint32_t* r, uint32_t addr) {
    asm volatile("ldmatrix.sync.aligned.m8n8.x2.shared.b16 {%0,%1}, [%2];"
                 : "=r"(r[0]), "=r"(r[1]) : "r"(addr));
}
__device__ __forceinline__ void mma16816(float* c, const uint32_t* a, const uint32_t* b) {
    asm volatile(
        "mma.sync.aligned.m16n8k16.row.col.f32.bf16.bf16.f32 "
        "{%0,%1,%2,%3}, {%4,%5,%6,%7}, {%8,%9}, {%0,%1,%2,%3};"
        : "+f"(c[0]), "+f"(c[1]), "+f"(c[2]), "+f"(c[3])
        : "r"(a[0]), "r"(a[1]), "r"(a[2]), "r"(a[3]), "r"(b[0]), "r"(b[1]));
}

// ---------------- bf16 HMMA GEMM: C[M,N] = epi(A @ B^T) ----------------
// A split hi/lo [M][K], B split transposed hi/lo [Npad][K].
// Logical K' = 3K: chunks select (Ah,Bh) / (Al,Bh) / (Ah,Bl).
// Tile 128x128, BK=64, 256 threads (8 warps, 2x4 grid, 64x32 per warp),
// SW128-swizzled smem, cp.async double buffer.
#define MT 128
#define NT 128
#define KC 64
#define STG_BYTES 32768            // A 16K | B 16K
#define GEMM_SMEM (2*STG_BYTES)

template<int HAS_BIAS, int DO_SILU, int HAS_RES, int OUT_SPLIT>
__global__ void __launch_bounds__(256)
gemm_mma(const __nv_bfloat16* __restrict__ Ah, const __nv_bfloat16* __restrict__ Al,
         const __nv_bfloat16* __restrict__ Bh, const __nv_bfloat16* __restrict__ Bl,
         const float* __restrict__ bias, const float* __restrict__ res,
         float* __restrict__ Cf, __nv_bfloat16* __restrict__ Chi, __nv_bfloat16* __restrict__ Clo,
         int M, int N, int K)
{
    extern __shared__ char smem[];
    const uint32_t sbase = smem_u32(smem);
    const int tid = threadIdx.x;
    const int lane = tid & 31;
    const int wid = tid >> 5;
    const int row0 = blockIdx.y * MT;
    const int col0 = blockIdx.x * NT;
    const int wr0 = (wid & 1) * 64;
    const int wc0 = (wid >> 1) * 32;

    float c[4][4][4];
    #pragma unroll
    for (int m = 0; m < 4; m++)
        #pragma unroll
        for (int j = 0; j < 4; j++)
            #pragma unroll
            for (int e = 0; e < 4; e++) c[m][j][e] = 0.f;

    const int nch = 3 * K / KC;

    // -------- stage loader --------
    auto load_stage = [&](int kc) {
        const int kkg = kc * KC;
        const int term = (kkg >= 2*K) ? 2 : ((kkg >= K) ? 1 : 0);
        const int koff = kkg - term * K;
        const __nv_bfloat16* Ap = (term == 1) ? Al : Ah;
        const __nv_bfloat16* Bp = (term == 2) ? Bl : Bh;
        const uint32_t abase = sbase + (kc & 1) * STG_BYTES;
        const uint32_t bbase = abase + 16384;
        #pragma unroll
        for (int i = 0; i < 4; i++) {
            int ch = tid + i * 256;          // 0..1023
            int r  = ch >> 3;                // 0..127
            int c16 = ch & 7;                // 0..7 (16B units within 128B row)
            uint32_t soff = (uint32_t)(r * 128 + ((c16 * 16) ^ ((r & 7) << 4)));
            cp_async16(abase + soff, Ap + (size_t)(row0 + r) * K + koff + c16 * 8);
            cp_async16(bbase + soff, Bp + (size_t)(col0 + r) * K + koff + c16 * 8);
        }
        cp_commit();
    };

    load_stage(0);

    for (int kc = 0; kc < nch; kc++) {
        if (kc + 1 < nch) { load_stage(kc + 1); cp_wait<1>(); }
        else              { cp_wait<0>(); }
        __syncthreads();

        const uint32_t abase = sbase + (kc & 1) * STG_BYTES;
        const uint32_t bbase = abase + 16384;

        #pragma unroll
        for (int ks = 0; ks < 4; ks++) {
            uint32_t a[4][4], b[4][2];
            #pragma unroll
            for (int m = 0; m < 4; m++) {
                int r = wr0 + m * 16 + (lane & 15);
                int cb = (ks * 2 + (lane >> 4)) * 16;
                ldsm4(a[m], abase + r * 128 + (cb ^ ((r & 7) << 4)));
            }
            #pragma unroll
            for (int j = 0; j < 4; j++) {
                int l = lane & 15;
                int r = wc0 + j * 8 + (l & 7);
                int cb = (ks * 2 + (l >> 3)) * 16;
                ldsm2(b[j], bbase + r * 128 + (cb ^ ((r & 7) << 4)));
            }
            #pragma unroll
            for (int m = 0; m < 4; m++)
                #pragma unroll
                for (int j = 0; j < 4; j++)
                    mma16816(c[m][j], a[m], b[j]);
        }
        __syncthreads();
    }

    // -------- epilogue --------
    #pragma unroll
    for (int m = 0; m < 4; m++) {
        const int r_ = row0 + wr0 + m * 16 + (lane >> 2);
        #pragma unroll
        for (int j = 0; j < 4; j++) {
            const int c_ = col0 + wc0 + j * 8 + 2 * (lane & 3);
            #pragma unroll
            for (int e = 0; e < 4; e++) {
                const int rr = r_ + (e >> 1) * 8;
                const int cc = c_ + (e & 1);
                if (cc < N) {
                    float v = c[m][j][e];
                    if (HAS_BIAS) v += bias[cc];
                    if (DO_SILU)  v = v / (1.f + expf(-v));
                    if (HAS_RES)  v += res[(size_t)rr * N + cc];
                    if (OUT_SPLIT) {
                        __nv_bfloat16 hh = __float2bfloat16(v);
                        Chi[(size_t)rr * N + cc] = hh;
                        Clo[(size_t)rr * N + cc] = __float2bfloat16(v - __bfloat162float(hh));
                    } else {
                        Cf[(size_t)rr * N + cc] = v;
                    }
                }
            }
        }
    }
}

// ---------------- split fp32 -> bf16 hi/lo ----------------
__global__ void split_k(const float* __restrict__ x, __nv_bfloat16* __restrict__ h,
                        __nv_bfloat16* __restrict__ l, int n)
{
    int i = blockIdx.x * blockDim.x + threadIdx.x;
    if (i >= n) return;
    float v = x[i];
    __nv_bfloat16 hh = __float2bfloat16(v);
    h[i] = hh;
    l[i] = __float2bfloat16(v - __bfloat162float(hh));
}

// ---------------- transpose + split: W[K][N] fp32 -> T[Npad][K] bf16 hi/lo ----------------
__global__ void trsplit_k(const float* __restrict__ W, __nv_bfloat16* __restrict__ Th,
                          __nv_bfloat16* __restrict__ Tl, int K, int N, int Npad)
{
    __shared__ float t[32][33];
    int kb = blockIdx.y * 32, nb = blockIdx.x * 32;
    int x = threadIdx.x & 31, y = threadIdx.x >> 5;   // 256 thr: 32x8
    #pragma unroll
    for (int i = y; i < 32; i += 8) {
        int kk = kb + i, nn = nb + x;
        t[i][x] = (kk < K && nn < N) ? W[(size_t)kk * N + nn] : 0.f;
    }
    __syncthreads();
    #pragma unroll
    for (int i = y; i < 32; i += 8) {
        int nn = nb + i, kk = kb + x;
        if (nn < Npad && kk < K) {
            float v = t[x][i];
            __nv_bfloat16 hh = __float2bfloat16(v);
            Th[(size_t)nn * K + kk] = hh;
            Tl[(size_t)nn * K + kk] = __float2bfloat16(v - __bfloat162float(hh));
        }
    }
}

// ---------------- depthwise causal conv (k=4) + bias + silu ----------------
__global__ void conv_k(const float* __restrict__ conv_w, const float* __restrict__ conv_b)
{
    int idx = blockIdx.x * blockDim.x + threadIdx.x;
    if (idx >= MTOK * CONV_DIM) return;
    int c = idx % CONV_DIM;
    int tok = idx / CONV_DIM;
    int t = tok % LL;
    long long base = (long long)tok * DPROJ + DIN + c;
    float acc = conv_b[c];
    #pragma unroll
    for (int k = 0; k < DCONVK; k++) {
        int tt = t - (DCONVK - 1) + k;
        if (tt >= 0)
            acc = fmaf(g_zx[base + (long long)(k - (DCONVK - 1)) * DPROJ], conv_w[c*DCONVK + k], acc);
    }
    g_xbc[idx] = acc / (1.f + expf(-acc));
}

// ---------------- dt / dA ----------------
__global__ void dt_k(const float* __restrict__ dt_bias, const float* __restrict__ A_log)
{
    int idx = blockIdx.x * blockDim.x + threadIdx.x;
    if (idx >= MTOK * NHH) return;
    int h = idx % NHH;
    int tok = idx / NHH;
    float x = g_zx[(size_t)tok * DPROJ + DIN + CONV_DIM + h] + dt_bias[h];
    float dt = (x > 20.f) ? x : log1pf(expf(x));
    g_dt[idx] = dt;
    g_dA[idx] = expf(-expf(A_log[h]) * dt);
}

// ---------------- sequential selective scan ----------------
__global__ void scan_k(const float* __restrict__ D_param)
{
    int b = blockIdx.x >> 5;
    int h = blockIdx.x & 31;
    int tid = threadIdx.x;
    int p = tid >> 3;
    int n0 = (tid & 7) * 8;
    float hs[8] = {};
    float Dv = D_param[h];

    for (int t = 0; t < LL; t++) {
        int tok = b * LL + t;
        const float* xrow = g_xbc + (size_t)tok * CONV_DIM;
        float dA = g_dA[tok*NHH + h];
        float dt = g_dt[tok*NHH + h];
        float xp = xrow[h*HD + p];
        float dtx = dt * xp;
        float4 B1 = *(const float4*)(xrow + DIN + n0);
        float4 B2 = *(const float4*)(xrow + DIN + n0 + 4);
        float4 C1 = *(const float4*)(xrow + DIN + DS + n0);
        float4 C2 = *(const float4*)(xrow + DIN + DS + n0 + 4);
        float Bv[8] = {B1.x,B1.y,B1.z,B1.w,B2.x,B2.y,B2.z,B2.w};
        float Cv[8] = {C1.x,C1.y,C1.z,C1.w,C2.x,C2.y,C2.z,C2.w};
        float part = 0.f;
        #pragma unroll
        for (int i = 0; i < 8; i++) {
            hs[i] = fmaf(dA, hs[i], dtx * Bv[i]);
            part  = fmaf(hs[i], Cv[i], part);
        }
        part += __shfl_down_sync(0xffffffffu, part, 4);
        part += __shfl_down_sync(0xffffffffu, part, 2);
        part += __shfl_down_sync(0xffffffffu, part, 1);
        if ((tid & 7) == 0)
            g_y[(size_t)tok * DIN + h*HD + p] = part + Dv * xp;
    }
}

// ---------------- gated RMSNorm -> yn bf16 hi/lo ----------------
__global__ void gatenorm_k(const float* __restrict__ norm_w)
{
    int tok = blockIdx.x;
    __shared__ float sv[DIN];
    __shared__ float red[256];
    const float* yrow = g_y  + (size_t)tok * DIN;
    const float* zrow = g_zx + (size_t)tok * DPROJ;
    float ss = 0.f;
    for (int c = threadIdx.x; c < DIN; c += 256) {
        float z = zrow[c];
        float v = yrow[c] * (z / (1.f + expf(-z)));
        sv[c] = v;
        ss += v * v;
    }
    red[threadIdx.x] = ss; __syncthreads();
    for (int s = 128; s > 0; s >>= 1) {
        if (threadIdx.x < s) red[threadIdx.x] += red[threadIdx.x + s];
        __syncthreads();
    }
    float scale = rsqrtf(red[0] / DIN + EPSV);
    for (int c = threadIdx.x; c < DIN; c += 256) {
        float v = sv[c] * scale * norm_w[c];
        __nv_bfloat16 hh = __float2bfloat16(v);
        g_yn_h[(size_t)tok * DIN + c] = hh;
        g_yn_l[(size_t)tok * DIN + c] = __float2bfloat16(v - __bfloat162float(hh));
    }
}

// ---------------- plain RMSNorm over DM -> hn bf16 hi/lo ----------------
__global__ void rmsnorm_k(const float* __restrict__ x, const float* __restrict__ w)
{
    int tok = blockIdx.x;
    __shared__ float sv[DM];
    __shared__ float red[256];
    const float* xr = x + (size_t)tok * DM;
    float ss = 0.f;
    for (int c = threadIdx.x; c < DM; c += 256) {
        float v = xr[c];
        sv[c] = v;
        ss += v * v;
    }
    red[threadIdx.x] = ss; __syncthreads();
    for (int s = 128; s > 0; s >>= 1) {
        if (threadIdx.x < s) red[threadIdx.x] += red[threadIdx.x + s];
        __syncthreads();
    }
    float scale = rsqrtf(red[0] / DM + EPSV);
    for (int c = threadIdx.x; c < DM; c += 256) {
        float v = sv[c] * scale * w[c];
        __nv_bfloat16 hh = __float2bfloat16(v);
        g_hn_h[(size_t)tok * DM + c] = hh;
        g_hn_l[(size_t)tok * DM + c] = __float2bfloat16(v - __bfloat162float(hh));
    }
}

// ---------------- launch ----------------
extern "C" void kernel_launch(void* const* d_in, const int* in_sizes, int n_in,
                              void* d_out, int out_size)
{
    const float* x       = (const float*)d_in[0];
    const float* W_in    = (const float*)d_in[1];
    const float* conv_w  = (const float*)d_in[2];
    const float* conv_b  = (const float*)d_in[3];
    const float* dt_bias = (const float*)d_in[4];
    const float* A_log   = (const float*)d_in[5];
    const float* D_param = (const float*)d_in[6];
    const float* norm_w  = (const float*)d_in[7];
    const float* W_out   = (const float*)d_in[8];
    const float* rms_w   = (const float*)d_in[9];
    const float* mlp_w1  = (const float*)d_in[10];
    const float* mlp_b1  = (const float*)d_in[11];
    const float* mlp_w2  = (const float*)d_in[12];
    const float* mlp_b2  = (const float*)d_in[13];
    float* out           = (float*)d_out;
    (void)in_sizes; (void)n_in; (void)out_size;

    float *p_zx, *p_h;
    __nv_bfloat16 *p_xs_h, *p_xs_l, *p_yn_h, *p_yn_l, *p_hn_h, *p_hn_l, *p_act_h, *p_act_l;
    __nv_bfloat16 *p_win_h, *p_win_l, *p_wout_h, *p_wout_l, *p_w1_h, *p_w1_l, *p_w2_h, *p_w2_l;
    cudaGetSymbolAddress((void**)&p_zx, g_zx);
    cudaGetSymbolAddress((void**)&p_h, g_h);
    cudaGetSymbolAddress((void**)&p_xs_h, g_xs_h);   cudaGetSymbolAddress((void**)&p_xs_l, g_xs_l);
    cudaGetSymbolAddress((void**)&p_yn_h, g_yn_h);   cudaGetSymbolAddress((void**)&p_yn_l, g_yn_l);
    cudaGetSymbolAddress((void**)&p_hn_h, g_hn_h);   cudaGetSymbolAddress((void**)&p_hn_l, g_hn_l);
    cudaGetSymbolAddress((void**)&p_act_h, g_act_h); cudaGetSymbolAddress((void**)&p_act_l, g_act_l);
    cudaGetSymbolAddress((void**)&p_win_h, g_win_h); cudaGetSymbolAddress((void**)&p_win_l, g_win_l);
    cudaGetSymbolAddress((void**)&p_wout_h, g_wout_h); cudaGetSymbolAddress((void**)&p_wout_l, g_wout_l);
    cudaGetSymbolAddress((void**)&p_w1_h, g_w1_h);   cudaGetSymbolAddress((void**)&p_w1_l, g_w1_l);
    cudaGetSymbolAddress((void**)&p_w2_h, g_w2_h);   cudaGetSymbolAddress((void**)&p_w2_l, g_w2_l);

    cudaFuncSetAttribute(gemm_mma<0,0,0,0>, cudaFuncAttributeMaxDynamicSharedMemorySize, GEMM_SMEM);
    cudaFuncSetAttribute(gemm_mma<0,0,1,0>, cudaFuncAttributeMaxDynamicSharedMemorySize, GEMM_SMEM);
    cudaFuncSetAttribute(gemm_mma<1,1,0,1>, cudaFuncAttributeMaxDynamicSharedMemorySize, GEMM_SMEM);
    cudaFuncSetAttribute(gemm_mma<1,0,1,0>, cudaFuncAttributeMaxDynamicSharedMemorySize, GEMM_SMEM);

    dim3 blk(256);

    // 0. splits / weight transposes
    split_k<<<(MTOK*DM + 255)/256, blk>>>(x, p_xs_h, p_xs_l, MTOK*DM);
    trsplit_k<<<dim3(DPROJ_PAD/32, DM/32),  blk>>>(W_in,   p_win_h,  p_win_l,  DM,   DPROJ, DPROJ_PAD);
    trsplit_k<<<dim3(DM/32,        DIN/32), blk>>>(W_out,  p_wout_h, p_wout_l, DIN,  DM,    DM);
    trsplit_k<<<dim3(MLPI/32,      DM/32),  blk>>>(mlp_w1, p_w1_h,   p_w1_l,   DM,   MLPI,  MLPI);
    trsplit_k<<<dim3(DM/32,        MLPI/32),blk>>>(mlp_w2, p_w2_h,   p_w2_l,   MLPI, DM,    DM);

    // 1. in-projection: zx = x @ W_in
    gemm_mma<0,0,0,0><<<dim3(DPROJ_PAD/NT, MTOK/MT), 256, GEMM_SMEM>>>(
        p_xs_h, p_xs_l, p_win_h, p_win_l, nullptr, nullptr, p_zx, nullptr, nullptr,
        MTOK, DPROJ, DM);
    // 2. conv + silu
    conv_k<<<(MTOK*CONV_DIM + 255)/256, blk>>>(conv_w, conv_b);
    // 3. dt / dA
    dt_k<<<(MTOK*NHH + 255)/256, blk>>>(dt_bias, A_log);
    // 4. scan
    scan_k<<<BB*NHH, 512>>>(D_param);
    // 5. gate + rmsnorm -> yn (split)
    gatenorm_k<<<MTOK, blk>>>(norm_w);
    // 6. h = x + yn @ W_out
    gemm_mma<0,0,1,0><<<dim3(DM/NT, MTOK/MT), 256, GEMM_SMEM>>>(
        p_yn_h, p_yn_l, p_wout_h, p_wout_l, nullptr, x, p_h, nullptr, nullptr,
        MTOK, DM, DIN);
    // 7. hn = rmsnorm(h) (split)
    rmsnorm_k<<<MTOK, blk>>>(p_h, rms_w);
    // 8. act = silu(hn @ mlp_w1 + b1) (split)
    gemm_mma<1,1,0,1><<<dim3(MLPI/NT, MTOK/MT), 256, GEMM_SMEM>>>(
        p_hn_h, p_hn_l, p_w1_h, p_w1_l, mlp_b1, nullptr, nullptr, p_act_h, p_act_l,
        MTOK, MLPI, DM);
    // 9. out = h + act @ mlp_w2 + b2
    gemm_mma<1,0,1,0><<<dim3(DM/NT, MTOK/MT), 256, GEMM_SMEM>>>(
        p_act_h, p_act_l, p_w2_h, p_w2_l, mlp_b2, p_h, out, nullptr, nullptr,
        MTOK, DM, MLPI);
}

// round 4
// speedup vs baseline: 2.0777x; 1.1339x over previous
#include <cuda_runtime.h>
#include <cuda_bf16.h>
#include <math.h>
#include <stddef.h>
#include <stdint.h>

// ---------------- problem constants ----------------
#define BB 2
#define LL 2048
#define DM 1024
#define DIN 2048
#define NHH 32
#define HD 64
#define DS 64
#define DCONVK 4
#define CONV_DIM (DIN + 2*DS)        // 2176
#define DPROJ (2*DIN + 2*DS + NHH)   // 4256
#define DPROJ_PAD 4352               // multiple of 128
#define MLPI 4096
#define MTOK (BB*LL)                 // 4096
#define EPSV 1e-5f

// ---------------- scratch (device globals) ----------------
__device__ float g_zx [MTOK*(size_t)DPROJ];
__device__ float g_xbc[MTOK*(size_t)CONV_DIM];
__device__ float g_dt [MTOK*NHH];
__device__ float g_dA [MTOK*NHH];
__device__ float g_y  [MTOK*(size_t)DIN];
__device__ float g_h  [MTOK*(size_t)DM];

__device__ __nv_bfloat16 g_xs_h [MTOK*(size_t)DM],   g_xs_l [MTOK*(size_t)DM];
__device__ __nv_bfloat16 g_yn_h [MTOK*(size_t)DIN],  g_yn_l [MTOK*(size_t)DIN];
__device__ __nv_bfloat16 g_hn_h [MTOK*(size_t)DM],   g_hn_l [MTOK*(size_t)DM];
__device__ __nv_bfloat16 g_act_h[MTOK*(size_t)MLPI], g_act_l[MTOK*(size_t)MLPI];

__device__ __nv_bfloat16 g_win_h [DPROJ_PAD*(size_t)DM],  g_win_l [DPROJ_PAD*(size_t)DM];
__device__ __nv_bfloat16 g_wout_h[DM*(size_t)DIN],        g_wout_l[DM*(size_t)DIN];
__device__ __nv_bfloat16 g_w1_h  [MLPI*(size_t)DM],       g_w1_l  [MLPI*(size_t)DM];
__device__ __nv_bfloat16 g_w2_h  [DM*(size_t)MLPI],       g_w2_l  [DM*(size_t)MLPI];

// ---------------- small asm helpers (baseline PTX, sm_80+) ----------------
__device__ __forceinline__ uint32_t smem_u32(const void* p) {
    uint32_t a;
    asm("{ .reg .u64 t; cvta.to.shared.u64 t, %1; cvt.u32.u64 %0, t; }" : "=r"(a) : "l"(p));
    return a;
}
__device__ __forceinline__ void cp_async16(uint32_t dst, const void* src) {
    asm volatile("cp.async.ca.shared.global [%0], [%1], 16;" :: "r"(dst), "l"(src) : "memory");
}
__device__ __forceinline__ void cp_commit() {
    asm volatile("cp.async.commit_group;" ::: "memory");
}
template<int N> __device__ __forceinline__ void cp_wait() {
    asm volatile("cp.async.wait_group %0;" :: "n"(N) : "memory");
}
__device__ __forceinline__ void ldsm4(uint32_t* r, uint32_t addr) {
    asm volatile("ldmatrix.sync.aligned.m8n8.x4.shared.b16 {%0,%1,%2,%3}, [%4];"
                 : "=r"(r[0]), "=r"(r[1]), "=r"(r[2]), "=r"(r[3]) : "r"(addr));
}
__device__ __forceinline__ void ldsm2(uint32_t* r, uint32_t addr) {
    asm volatile("ldmatrix.sync.aligned.m8n8.x2.shared.b16 {%0,%1}, [%2];"
                 : "=r"(r[0]), "=r"(r[1]) : "r"(addr));
}
__device__ __forceinline__ void mma16816(float* c, const uint32_t* a, const uint32_t* b) {
    asm volatile(
        "mma.sync.aligned.m16n8k16.row.col.f32.bf16.bf16.f32 "
        "{%0,%1,%2,%3}, {%4,%5,%6,%7}, {%8,%9}, {%0,%1,%2,%3};"
        : "+f"(c[0]), "+f"(c[1]), "+f"(c[2]), "+f"(c[3])
        : "r"(a[0]), "r"(a[1]), "r"(a[2]), "r"(a[3]), "r"(b[0]), "r"(b[1]));
}

// ---------------- bf16 HMMA split GEMM: C[M,N] = epi(A @ B^T) ----------------
// A split hi/lo [M][K], B split transposed hi/lo [Npad][K].
// 3-term split (Ah.Bh + Al.Bh + Ah.Bl), all terms issued from ONE smem stage
// per K-chunk (hi+lo loaded once). Tile 256x128, BK=64, 512 threads
// (16 warps, 4x4 grid, 64x32 per warp), SW128 swizzle, cp.async double buffer.
#define MT 256
#define NT 128
#define KC 64
// stage: Ah 32K | Al 32K | Bh 16K | Bl 16K = 96K
#define STG_BYTES 98304
#define GEMM_SMEM (2*STG_BYTES)    // 192 KB

template<int HAS_BIAS, int DO_SILU, int HAS_RES, int OUT_SPLIT>
__global__ void __launch_bounds__(512)
gemm_mma(const __nv_bfloat16* __restrict__ Ah, const __nv_bfloat16* __restrict__ Al,
         const __nv_bfloat16* __restrict__ Bh, const __nv_bfloat16* __restrict__ Bl,
         const float* __restrict__ bias, const float* __restrict__ res,
         float* __restrict__ Cf, __nv_bfloat16* __restrict__ Chi, __nv_bfloat16* __restrict__ Clo,
         int M, int N, int K)
{
    extern __shared__ char smem[];
    const uint32_t sbase = smem_u32(smem);
    const int tid = threadIdx.x;
    const int lane = tid & 31;
    const int wid = tid >> 5;
    const int row0 = blockIdx.y * MT;
    const int col0 = blockIdx.x * NT;
    const int wr0 = (wid & 3) * 64;
    const int wc0 = (wid >> 2) * 32;

    float c[4][4][4];
    #pragma unroll
    for (int m = 0; m < 4; m++)
        #pragma unroll
        for (int j = 0; j < 4; j++)
            #pragma unroll
            for (int e = 0; e < 4; e++) c[m][j][e] = 0.f;

    const int nch = K / KC;

    auto load_stage = [&](int kc) {
        const int koff = kc * KC;
        const uint32_t st = sbase + (kc & 1) * STG_BYTES;
        #pragma unroll
        for (int i = 0; i < 4; i++) {                  // A: 256 rows x 128B
            int ch = tid + i * 512;                    // 0..2047
            int r = ch >> 3, c16 = ch & 7;
            uint32_t soff = (uint32_t)(r * 128 + ((c16 * 16) ^ ((r & 7) << 4)));
            const size_t go = (size_t)(row0 + r) * K + koff + c16 * 8;
            cp_async16(st + soff,         Ah + go);
            cp_async16(st + 32768 + soff, Al + go);
        }
        #pragma unroll
        for (int i = 0; i < 2; i++) {                  // B: 128 rows x 128B
            int ch = tid + i * 512;                    // 0..1023
            int r = ch >> 3, c16 = ch & 7;
            uint32_t soff = (uint32_t)(r * 128 + ((c16 * 16) ^ ((r & 7) << 4)));
            const size_t go = (size_t)(col0 + r) * K + koff + c16 * 8;
            cp_async16(st + 65536 + soff, Bh + go);
            cp_async16(st + 81920 + soff, Bl + go);
        }
        cp_commit();
    };

    load_stage(0);

    for (int kc = 0; kc < nch; kc++) {
        if (kc + 1 < nch) { load_stage(kc + 1); cp_wait<1>(); }
        else              { cp_wait<0>(); }
        __syncthreads();

        const uint32_t st = sbase + (kc & 1) * STG_BYTES;

        #pragma unroll
        for (int ks = 0; ks < 4; ks++) {
            uint32_t a[4][4], bh[4][2], bl[4][2];
            // aH fragments
            #pragma unroll
            for (int m = 0; m < 4; m++) {
                int r = wr0 + m * 16 + (lane & 15);
                int cb = (ks * 2 + (lane >> 4)) * 16;
                ldsm4(a[m], st + r * 128 + (cb ^ ((r & 7) << 4)));
            }
            // bH / bL fragments
            #pragma unroll
            for (int j = 0; j < 4; j++) {
                int l = lane & 15;
                int r = wc0 + j * 8 + (l & 7);
                int cb = (ks * 2 + (l >> 3)) * 16;
                uint32_t sw = (uint32_t)(r * 128 + (cb ^ ((r & 7) << 4)));
                ldsm2(bh[j], st + 65536 + sw);
                ldsm2(bl[j], st + 81920 + sw);
            }
            // Ah.Bh and Ah.Bl
            #pragma unroll
            for (int m = 0; m < 4; m++)
                #pragma unroll
                for (int j = 0; j < 4; j++) {
                    mma16816(c[m][j], a[m], bh[j]);
                    mma16816(c[m][j], a[m], bl[j]);
                }
            // aL fragments (reuse regs), Al.Bh
            #pragma unroll
            for (int m = 0; m < 4; m++) {
                int r = wr0 + m * 16 + (lane & 15);
                int cb = (ks * 2 + (lane >> 4)) * 16;
                ldsm4(a[m], st + 32768 + r * 128 + (cb ^ ((r & 7) << 4)));
            }
            #pragma unroll
            for (int m = 0; m < 4; m++)
                #pragma unroll
                for (int j = 0; j < 4; j++)
                    mma16816(c[m][j], a[m], bh[j]);
        }
        __syncthreads();
    }

    // -------- epilogue --------
    #pragma unroll
    for (int m = 0; m < 4; m++) {
        const int r_ = row0 + wr0 + m * 16 + (lane >> 2);
        #pragma unroll
        for (int j = 0; j < 4; j++) {
            const int c_ = col0 + wc0 + j * 8 + 2 * (lane & 3);
            #pragma unroll
            for (int e = 0; e < 4; e++) {
                const int rr = r_ + (e >> 1) * 8;
                const int cc = c_ + (e & 1);
                if (cc < N) {
                    float v = c[m][j][e];
                    if (HAS_BIAS) v += bias[cc];
                    if (DO_SILU)  v = v / (1.f + expf(-v));
                    if (HAS_RES)  v += res[(size_t)rr * N + cc];
                    if (OUT_SPLIT) {
                        __nv_bfloat16 hh = __float2bfloat16(v);
                        Chi[(size_t)rr * N + cc] = hh;
                        Clo[(size_t)rr * N + cc] = __float2bfloat16(v - __bfloat162float(hh));
                    } else {
                        Cf[(size_t)rr * N + cc] = v;
                    }
                }
            }
        }
    }
}

// ---------------- split fp32 -> bf16 hi/lo ----------------
__global__ void split_k(const float* __restrict__ x, __nv_bfloat16* __restrict__ h,
                        __nv_bfloat16* __restrict__ l, int n)
{
    int i = blockIdx.x * blockDim.x + threadIdx.x;
    if (i >= n) return;
    float v = x[i];
    __nv_bfloat16 hh = __float2bfloat16(v);
    h[i] = hh;
    l[i] = __float2bfloat16(v - __bfloat162float(hh));
}

// ---------------- transpose + split: W[K][N] fp32 -> T[Npad][K] bf16 hi/lo ----------------
__global__ void trsplit_k(const float* __restrict__ W, __nv_bfloat16* __restrict__ Th,
                          __nv_bfloat16* __restrict__ Tl, int K, int N, int Npad)
{
    __shared__ float t[32][33];
    int kb = blockIdx.y * 32, nb = blockIdx.x * 32;
    int x = threadIdx.x & 31, y = threadIdx.x >> 5;
    #pragma unroll
    for (int i = y; i < 32; i += 8) {
        int kk = kb + i, nn = nb + x;
        t[i][x] = (kk < K && nn < N) ? W[(size_t)kk * N + nn] : 0.f;
    }
    __syncthreads();
    #pragma unroll
    for (int i = y; i < 32; i += 8) {
        int nn = nb + i, kk = kb + x;
        if (nn < Npad && kk < K) {
            float v = t[x][i];
            __nv_bfloat16 hh = __float2bfloat16(v);
            Th[(size_t)nn * K + kk] = hh;
            Tl[(size_t)nn * K + kk] = __float2bfloat16(v - __bfloat162float(hh));
        }
    }
}

// ---------------- depthwise causal conv (k=4) + bias + silu ----------------
__global__ void conv_k(const float* __restrict__ conv_w, const float* __restrict__ conv_b)
{
    int idx = blockIdx.x * blockDim.x + threadIdx.x;
    if (idx >= MTOK * CONV_DIM) return;
    int c = idx % CONV_DIM;
    int tok = idx / CONV_DIM;
    int t = tok % LL;
    long long base = (long long)tok * DPROJ + DIN + c;
    float acc = conv_b[c];
    #pragma unroll
    for (int k = 0; k < DCONVK; k++) {
        int tt = t - (DCONVK - 1) + k;
        if (tt >= 0)
            acc = fmaf(g_zx[base + (long long)(k - (DCONVK - 1)) * DPROJ], conv_w[c*DCONVK + k], acc);
    }
    g_xbc[idx] = acc / (1.f + expf(-acc));
}

// ---------------- dt / dA ----------------
__global__ void dt_k(const float* __restrict__ dt_bias, const float* __restrict__ A_log)
{
    int idx = blockIdx.x * blockDim.x + threadIdx.x;
    if (idx >= MTOK * NHH) return;
    int h = idx % NHH;
    int tok = idx / NHH;
    float x = g_zx[(size_t)tok * DPROJ + DIN + CONV_DIM + h] + dt_bias[h];
    float dt = (x > 20.f) ? x : log1pf(expf(x));
    g_dt[idx] = dt;
    g_dA[idx] = expf(-expf(A_log[h]) * dt);
}

// ---------------- sequential selective scan (register-prefetch pipelined) ----------------
__global__ void scan_k(const float* __restrict__ D_param)
{
    int b = blockIdx.x >> 5;
    int h = blockIdx.x & 31;
    int tid = threadIdx.x;
    int p = tid >> 3;
    int n0 = (tid & 7) * 8;
    float hs[8] = {};
    float Dv = D_param[h];

    const float* xrow = g_xbc + (size_t)(b * LL) * CONV_DIM;
    int tok0 = b * LL;

    float dA_c = g_dA[tok0*NHH + h];
    float dt_c = g_dt[tok0*NHH + h];
    float xp_c = xrow[h*HD + p];
    float4 B1c = *(const float4*)(xrow + DIN + n0);
    float4 B2c = *(const float4*)(xrow + DIN + n0 + 4);
    float4 C1c = *(const float4*)(xrow + DIN + DS + n0);
    float4 C2c = *(const float4*)(xrow + DIN + DS + n0 + 4);

    for (int t = 0; t < LL; t++) {
        // prefetch t+1 (independent loads, scheduled before compute)
        float dA_n = 0.f, dt_n = 0.f, xp_n = 0.f;
        float4 B1n = {}, B2n = {}, C1n = {}, C2n = {};
        const float* xn = xrow + CONV_DIM;
        if (t + 1 < LL) {
            int tokn = tok0 + t + 1;
            dA_n = g_dA[tokn*NHH + h];
            dt_n = g_dt[tokn*NHH + h];
            xp_n = xn[h*HD + p];
            B1n = *(const float4*)(xn + DIN + n0);
            B2n = *(const float4*)(xn + DIN + n0 + 4);
            C1n = *(const float4*)(xn + DIN + DS + n0);
            C2n = *(const float4*)(xn + DIN + DS + n0 + 4);
        }

        float dtx = dt_c * xp_c;
        float Bv[8] = {B1c.x,B1c.y,B1c.z,B1c.w,B2c.x,B2c.y,B2c.z,B2c.w};
        float Cv[8] = {C1c.x,C1c.y,C1c.z,C1c.w,C2c.x,C2c.y,C2c.z,C2c.w};
        float part = 0.f;
        #pragma unroll
        for (int i = 0; i < 8; i++) {
            hs[i] = fmaf(dA_c, hs[i], dtx * Bv[i]);
            part  = fmaf(hs[i], Cv[i], part);
        }
        part += __shfl_down_sync(0xffffffffu, part, 4);
        part += __shfl_down_sync(0xffffffffu, part, 2);
        part += __shfl_down_sync(0xffffffffu, part, 1);
        if ((tid & 7) == 0)
            g_y[(size_t)(tok0 + t) * DIN + h*HD + p] = part + Dv * xp_c;

        dA_c = dA_n; dt_c = dt_n; xp_c = xp_n;
        B1c = B1n; B2c = B2n; C1c = C1n; C2c = C2n;
        xrow = xn;
    }
}

// ---------------- gated RMSNorm -> yn bf16 hi/lo ----------------
__global__ void gatenorm_k(const float* __restrict__ norm_w)
{
    int tok = blockIdx.x;
    __shared__ float sv[DIN];
    __shared__ float red[256];
    const float* yrow = g_y  + (size_t)tok * DIN;
    const float* zrow = g_zx + (size_t)tok * DPROJ;
    float ss = 0.f;
    for (int c = threadIdx.x; c < DIN; c += 256) {
        float z = zrow[c];
        float v = yrow[c] * (z / (1.f + expf(-z)));
        sv[c] = v;
        ss += v * v;
    }
    red[threadIdx.x] = ss; __syncthreads();
    for (int s = 128; s > 0; s >>= 1) {
        if (threadIdx.x < s) red[threadIdx.x] += red[threadIdx.x + s];
        __syncthreads();
    }
    float scale = rsqrtf(red[0] / DIN + EPSV);
    for (int c = threadIdx.x; c < DIN; c += 256) {
        float v = sv[c] * scale * norm_w[c];
        __nv_bfloat16 hh = __float2bfloat16(v);
        g_yn_h[(size_t)tok * DIN + c] = hh;
        g_yn_l[(size_t)tok * DIN + c] = __float2bfloat16(v - __bfloat162float(hh));
    }
}

// ---------------- plain RMSNorm over DM -> hn bf16 hi/lo ----------------
__global__ void rmsnorm_k(const float* __restrict__ x, const float* __restrict__ w)
{
    int tok = blockIdx.x;
    __shared__ float sv[DM];
    __shared__ float red[256];
    const float* xr = x + (size_t)tok * DM;
    float ss = 0.f;
    for (int c = threadIdx.x; c < DM; c += 256) {
        float v = xr[c];
        sv[c] = v;
        ss += v * v;
    }
    red[threadIdx.x] = ss; __syncthreads();
    for (int s = 128; s > 0; s >>= 1) {
        if (threadIdx.x < s) red[threadIdx.x] += red[threadIdx.x + s];
        __syncthreads();
    }
    float scale = rsqrtf(red[0] / DM + EPSV);
    for (int c = threadIdx.x; c < DM; c += 256) {
        float v = sv[c] * scale * w[c];
        __nv_bfloat16 hh = __float2bfloat16(v);
        g_hn_h[(size_t)tok * DM + c] = hh;
        g_hn_l[(size_t)tok * DM + c] = __float2bfloat16(v - __bfloat162float(hh));
    }
}

// ---------------- launch ----------------
extern "C" void kernel_launch(void* const* d_in, const int* in_sizes, int n_in,
                              void* d_out, int out_size)
{
    const float* x       = (const float*)d_in[0];
    const float* W_in    = (const float*)d_in[1];
    const float* conv_w  = (const float*)d_in[2];
    const float* conv_b  = (const float*)d_in[3];
    const float* dt_bias = (const float*)d_in[4];
    const float* A_log   = (const float*)d_in[5];
    const float* D_param = (const float*)d_in[6];
    const float* norm_w  = (const float*)d_in[7];
    const float* W_out   = (const float*)d_in[8];
    const float* rms_w   = (const float*)d_in[9];
    const float* mlp_w1  = (const float*)d_in[10];
    const float* mlp_b1  = (const float*)d_in[11];
    const float* mlp_w2  = (const float*)d_in[12];
    const float* mlp_b2  = (const float*)d_in[13];
    float* out           = (float*)d_out;
    (void)in_sizes; (void)n_in; (void)out_size;

    float *p_zx, *p_h;
    __nv_bfloat16 *p_xs_h, *p_xs_l, *p_yn_h, *p_yn_l, *p_hn_h, *p_hn_l, *p_act_h, *p_act_l;
    __nv_bfloat16 *p_win_h, *p_win_l, *p_wout_h, *p_wout_l, *p_w1_h, *p_w1_l, *p_w2_h, *p_w2_l;
    cudaGetSymbolAddress((void**)&p_zx, g_zx);
    cudaGetSymbolAddress((void**)&p_h, g_h);
    cudaGetSymbolAddress((void**)&p_xs_h, g_xs_h);   cudaGetSymbolAddress((void**)&p_xs_l, g_xs_l);
    cudaGetSymbolAddress((void**)&p_yn_h, g_yn_h);   cudaGetSymbolAddress((void**)&p_yn_l, g_yn_l);
    cudaGetSymbolAddress((void**)&p_hn_h, g_hn_h);   cudaGetSymbolAddress((void**)&p_hn_l, g_hn_l);
    cudaGetSymbolAddress((void**)&p_act_h, g_act_h); cudaGetSymbolAddress((void**)&p_act_l, g_act_l);
    cudaGetSymbolAddress((void**)&p_win_h, g_win_h); cudaGetSymbolAddress((void**)&p_win_l, g_win_l);
    cudaGetSymbolAddress((void**)&p_wout_h, g_wout_h); cudaGetSymbolAddress((void**)&p_wout_l, g_wout_l);
    cudaGetSymbolAddress((void**)&p_w1_h, g_w1_h);   cudaGetSymbolAddress((void**)&p_w1_l, g_w1_l);
    cudaGetSymbolAddress((void**)&p_w2_h, g_w2_h);   cudaGetSymbolAddress((void**)&p_w2_l, g_w2_l);

    cudaFuncSetAttribute(gemm_mma<0,0,0,0>, cudaFuncAttributeMaxDynamicSharedMemorySize, GEMM_SMEM);
    cudaFuncSetAttribute(gemm_mma<0,0,1,0>, cudaFuncAttributeMaxDynamicSharedMemorySize, GEMM_SMEM);
    cudaFuncSetAttribute(gemm_mma<1,1,0,1>, cudaFuncAttributeMaxDynamicSharedMemorySize, GEMM_SMEM);
    cudaFuncSetAttribute(gemm_mma<1,0,1,0>, cudaFuncAttributeMaxDynamicSharedMemorySize, GEMM_SMEM);

    dim3 blk(256);

    // 0. splits / weight transposes
    split_k<<<(MTOK*DM + 255)/256, blk>>>(x, p_xs_h, p_xs_l, MTOK*DM);
    trsplit_k<<<dim3(DPROJ_PAD/32, DM/32),  blk>>>(W_in,   p_win_h,  p_win_l,  DM,   DPROJ, DPROJ_PAD);
    trsplit_k<<<dim3(DM/32,        DIN/32), blk>>>(W_out,  p_wout_h, p_wout_l, DIN,  DM,    DM);
    trsplit_k<<<dim3(MLPI/32,      DM/32),  blk>>>(mlp_w1, p_w1_h,   p_w1_l,   DM,   MLPI,  MLPI);
    trsplit_k<<<dim3(DM/32,        MLPI/32),blk>>>(mlp_w2, p_w2_h,   p_w2_l,   MLPI, DM,    DM);

    // 1. in-projection: zx = x @ W_in
    gemm_mma<0,0,0,0><<<dim3(DPROJ_PAD/NT, MTOK/MT), 512, GEMM_SMEM>>>(
        p_xs_h, p_xs_l, p_win_h, p_win_l, nullptr, nullptr, p_zx, nullptr, nullptr,
        MTOK, DPROJ, DM);
    // 2. conv + silu
    conv_k<<<(MTOK*CONV_DIM + 255)/256, blk>>>(conv_w, conv_b);
    // 3. dt / dA
    dt_k<<<(MTOK*NHH + 255)/256, blk>>>(dt_bias, A_log);
    // 4. scan
    scan_k<<<BB*NHH, 512>>>(D_param);
    // 5. gate + rmsnorm -> yn (split)
    gatenorm_k<<<MTOK, blk>>>(norm_w);
    // 6. h = x + yn @ W_out
    gemm_mma<0,0,1,0><<<dim3(DM/NT, MTOK/MT), 512, GEMM_SMEM>>>(
        p_yn_h, p_yn_l, p_wout_h, p_wout_l, nullptr, x, p_h, nullptr, nullptr,
        MTOK, DM, DIN);
    // 7. hn = rmsnorm(h) (split)
    rmsnorm_k<<<MTOK, blk>>>(p_h, rms_w);
    // 8. act = silu(hn @ mlp_w1 + b1) (split)
    gemm_mma<1,1,0,1><<<dim3(MLPI/NT, MTOK/MT), 512, GEMM_SMEM>>>(
        p_hn_h, p_hn_l, p_w1_h, p_w1_l, mlp_b1, nullptr, nullptr, p_act_h, p_act_l,
        MTOK, MLPI, DM);
    // 9. out = h + act @ mlp_w2 + b2
    gemm_mma<1,0,1,0><<<dim3(DM/NT, MTOK/MT), 512, GEMM_SMEM>>>(
        p_act_h, p_act_l, p_w2_h, p_w2_l, mlp_b2, p_h, out, nullptr, nullptr,
        MTOK, DM, MLPI);
}

// round 5
// speedup vs baseline: 2.5011x; 1.2038x over previous
#include <cuda_runtime.h>
#include <cuda_fp16.h>
#include <math.h>
#include <stddef.h>
#include <stdint.h>

// ---------------- problem constants ----------------
#define BB 2
#define LL 2048
#define DM 1024
#define DIN 2048
#define NHH 32
#define HD 64
#define DS 64
#define DCONVK 4
#define CONV_DIM (DIN + 2*DS)        // 2176
#define DPROJ (2*DIN + 2*DS + NHH)   // 4256
#define DPROJ_PAD 4352               // multiple of 128
#define MLPI 4096
#define MTOK (BB*LL)                 // 4096
#define EPSV 1e-5f

// ---------------- scratch (device globals) ----------------
__device__ float g_zx [MTOK*(size_t)DPROJ];
__device__ float g_xbc[MTOK*(size_t)CONV_DIM];
__device__ float g_dt [MTOK*NHH];
__device__ float g_dA [MTOK*NHH];
__device__ float g_y  [MTOK*(size_t)DIN];
__device__ float g_h  [MTOK*(size_t)DM];

__device__ __half g_xs_h [MTOK*(size_t)DM],   g_xs_l [MTOK*(size_t)DM];
__device__ __half g_yn_h [MTOK*(size_t)DIN],  g_yn_l [MTOK*(size_t)DIN];
__device__ __half g_hn_h [MTOK*(size_t)DM],   g_hn_l [MTOK*(size_t)DM];
__device__ __half g_act_h[MTOK*(size_t)MLPI], g_act_l[MTOK*(size_t)MLPI];

__device__ __half g_win [DPROJ_PAD*(size_t)DM];
__device__ __half g_wout[DM*(size_t)DIN];
__device__ __half g_w1  [MLPI*(size_t)DM];
__device__ __half g_w2  [DM*(size_t)MLPI];

// ---------------- small asm helpers (baseline PTX, sm_80+) ----------------
__device__ __forceinline__ uint32_t smem_u32(const void* p) {
    uint32_t a;
    asm("{ .reg .u64 t; cvta.to.shared.u64 t, %1; cvt.u32.u64 %0, t; }" : "=r"(a) : "l"(p));
    return a;
}
__device__ __forceinline__ void cp_async16(uint32_t dst, const void* src) {
    asm volatile("cp.async.ca.shared.global [%0], [%1], 16;" :: "r"(dst), "l"(src) : "memory");
}
__device__ __forceinline__ void cp_commit() {
    asm volatile("cp.async.commit_group;" ::: "memory");
}
template<int N> __device__ __forceinline__ void cp_wait() {
    asm volatile("cp.async.wait_group %0;" :: "n"(N) : "memory");
}
__device__ __forceinline__ void ldsm4(uint32_t* r, uint32_t addr) {
    asm volatile("ldmatrix.sync.aligned.m8n8.x4.shared.b16 {%0,%1,%2,%3}, [%4];"
                 : "=r"(r[0]), "=r"(r[1]), "=r"(r[2]), "=r"(r[3]) : "r"(addr));
}
__device__ __forceinline__ void ldsm2(uint32_t* r, uint32_t addr) {
    asm volatile("ldmatrix.sync.aligned.m8n8.x2.shared.b16 {%0,%1}, [%2];"
                 : "=r"(r[0]), "=r"(r[1]) : "r"(addr));
}
__device__ __forceinline__ void mma16816(float* c, const uint32_t* a, const uint32_t* b) {
    asm volatile(
        "mma.sync.aligned.m16n8k16.row.col.f32.f16.f16.f32 "
        "{%0,%1,%2,%3}, {%4,%5,%6,%7}, {%8,%9}, {%0,%1,%2,%3};"
        : "+f"(c[0]), "+f"(c[1]), "+f"(c[2]), "+f"(c[3])
        : "r"(a[0]), "r"(a[1]), "r"(a[2]), "r"(a[3]), "r"(b[0]), "r"(b[1]));
}

// ---------------- fp16 HMMA 2-term split GEMM: C[M,N] = epi(A @ B^T) ----------------
// A split hi/lo fp16 [M][K]; B single fp16 transposed [Npad][K].
// C = Ah.Bh + Al.Bh (dropped A.Bl ~ 2^-12 rel).
// Tile 256x128, BK=64, 512 threads (16 warps, 4x4 grid, 64x32/warp),
// SW128 swizzle, cp.async double buffer.
#define MT 256
#define NT 128
#define KC 64
// stage: Ah 32K | Al 32K | Bh 16K = 80K
#define STG_BYTES 81920
#define GEMM_SMEM (2*STG_BYTES)    // 160 KB

template<int HAS_BIAS, int DO_SILU, int HAS_RES, int OUT_SPLIT>
__global__ void __launch_bounds__(512)
gemm_mma(const __half* __restrict__ Ah, const __half* __restrict__ Al,
         const __half* __restrict__ Bh,
         const float* __restrict__ bias, const float* __restrict__ res,
         float* __restrict__ Cf, __half* __restrict__ Chi, __half* __restrict__ Clo,
         int M, int N, int K)
{
    extern __shared__ char smem[];
    const uint32_t sbase = smem_u32(smem);
    const int tid = threadIdx.x;
    const int lane = tid & 31;
    const int wid = tid >> 5;
    const int row0 = blockIdx.y * MT;
    const int col0 = blockIdx.x * NT;
    const int wr0 = (wid & 3) * 64;
    const int wc0 = (wid >> 2) * 32;

    float c[4][4][4];
    #pragma unroll
    for (int m = 0; m < 4; m++)
        #pragma unroll
        for (int j = 0; j < 4; j++)
            #pragma unroll
            for (int e = 0; e < 4; e++) c[m][j][e] = 0.f;

    const int nch = K / KC;

    auto load_stage = [&](int kc) {
        const int koff = kc * KC;
        const uint32_t st = sbase + (kc & 1) * STG_BYTES;
        #pragma unroll
        for (int i = 0; i < 4; i++) {                  // A: 256 rows x 128B
            int ch = tid + i * 512;                    // 0..2047
            int r = ch >> 3, c16 = ch & 7;
            uint32_t soff = (uint32_t)(r * 128 + ((c16 * 16) ^ ((r & 7) << 4)));
            const size_t go = (size_t)(row0 + r) * K + koff + c16 * 8;
            cp_async16(st + soff,         Ah + go);
            cp_async16(st + 32768 + soff, Al + go);
        }
        #pragma unroll
        for (int i = 0; i < 2; i++) {                  // B: 128 rows x 128B
            int ch = tid + i * 512;                    // 0..1023
            int r = ch >> 3, c16 = ch & 7;
            uint32_t soff = (uint32_t)(r * 128 + ((c16 * 16) ^ ((r & 7) << 4)));
            cp_async16(st + 65536 + soff, Bh + (size_t)(col0 + r) * K + koff + c16 * 8);
        }
        cp_commit();
    };

    load_stage(0);

    for (int kc = 0; kc < nch; kc++) {
        if (kc + 1 < nch) { load_stage(kc + 1); cp_wait<1>(); }
        else              { cp_wait<0>(); }
        __syncthreads();

        const uint32_t st = sbase + (kc & 1) * STG_BYTES;

        #pragma unroll
        for (int ks = 0; ks < 4; ks++) {
            uint32_t a[4][4], b[4][2];
            // B fragments (reused by both terms)
            #pragma unroll
            for (int j = 0; j < 4; j++) {
                int l = lane & 15;
                int r = wc0 + j * 8 + (l & 7);
                int cb = (ks * 2 + (l >> 3)) * 16;
                ldsm2(b[j], st + 65536 + (uint32_t)(r * 128 + (cb ^ ((r & 7) << 4))));
            }
            // Ah fragments + Ah.Bh
            #pragma unroll
            for (int m = 0; m < 4; m++) {
                int r = wr0 + m * 16 + (lane & 15);
                int cb = (ks * 2 + (lane >> 4)) * 16;
                ldsm4(a[m], st + r * 128 + (cb ^ ((r & 7) << 4)));
            }
            #pragma unroll
            for (int m = 0; m < 4; m++)
                #pragma unroll
                for (int j = 0; j < 4; j++)
                    mma16816(c[m][j], a[m], b[j]);
            // Al fragments + Al.Bh
            #pragma unroll
            for (int m = 0; m < 4; m++) {
                int r = wr0 + m * 16 + (lane & 15);
                int cb = (ks * 2 + (lane >> 4)) * 16;
                ldsm4(a[m], st + 32768 + r * 128 + (cb ^ ((r & 7) << 4)));
            }
            #pragma unroll
            for (int m = 0; m < 4; m++)
                #pragma unroll
                for (int j = 0; j < 4; j++)
                    mma16816(c[m][j], a[m], b[j]);
        }
        __syncthreads();
    }

    // -------- epilogue --------
    #pragma unroll
    for (int m = 0; m < 4; m++) {
        const int r_ = row0 + wr0 + m * 16 + (lane >> 2);
        #pragma unroll
        for (int j = 0; j < 4; j++) {
            const int c_ = col0 + wc0 + j * 8 + 2 * (lane & 3);
            #pragma unroll
            for (int e = 0; e < 4; e++) {
                const int rr = r_ + (e >> 1) * 8;
                const int cc = c_ + (e & 1);
                if (cc < N) {
                    float v = c[m][j][e];
                    if (HAS_BIAS) v += bias[cc];
                    if (DO_SILU)  v = v / (1.f + expf(-v));
                    if (HAS_RES)  v += res[(size_t)rr * N + cc];
                    if (OUT_SPLIT) {
                        __half hh = __float2half(v);
                        Chi[(size_t)rr * N + cc] = hh;
                        Clo[(size_t)rr * N + cc] = __float2half(v - __half2float(hh));
                    } else {
                        Cf[(size_t)rr * N + cc] = v;
                    }
                }
            }
        }
    }
}

// ---------------- split fp32 -> fp16 hi/lo ----------------
__global__ void split_k(const float* __restrict__ x, __half* __restrict__ h,
                        __half* __restrict__ l, int n)
{
    int i = blockIdx.x * blockDim.x + threadIdx.x;
    if (i >= n) return;
    float v = x[i];
    __half hh = __float2half(v);
    h[i] = hh;
    l[i] = __float2half(v - __half2float(hh));
}

// ---------------- transpose + convert: W[K][N] fp32 -> T[Npad][K] fp16 ----------------
__global__ void trconv_k(const float* __restrict__ W, __half* __restrict__ Th,
                         int K, int N, int Npad)
{
    __shared__ float t[32][33];
    int kb = blockIdx.y * 32, nb = blockIdx.x * 32;
    int x = threadIdx.x & 31, y = threadIdx.x >> 5;
    #pragma unroll
    for (int i = y; i < 32; i += 8) {
        int kk = kb + i, nn = nb + x;
        t[i][x] = (kk < K && nn < N) ? W[(size_t)kk * N + nn] : 0.f;
    }
    __syncthreads();
    #pragma unroll
    for (int i = y; i < 32; i += 8) {
        int nn = nb + i, kk = kb + x;
        if (nn < Npad && kk < K)
            Th[(size_t)nn * K + kk] = __float2half(t[x][i]);
    }
}

// ---------------- depthwise causal conv (k=4) + bias + silu ----------------
__global__ void conv_k(const float* __restrict__ conv_w, const float* __restrict__ conv_b)
{
    int idx = blockIdx.x * blockDim.x + threadIdx.x;
    if (idx >= MTOK * CONV_DIM) return;
    int c = idx % CONV_DIM;
    int tok = idx / CONV_DIM;
    int t = tok % LL;
    long long base = (long long)tok * DPROJ + DIN + c;
    float acc = conv_b[c];
    #pragma unroll
    for (int k = 0; k < DCONVK; k++) {
        int tt = t - (DCONVK - 1) + k;
        if (tt >= 0)
            acc = fmaf(g_zx[base + (long long)(k - (DCONVK - 1)) * DPROJ], conv_w[c*DCONVK + k], acc);
    }
    g_xbc[idx] = acc / (1.f + expf(-acc));
}

// ---------------- dt / dA ----------------
__global__ void dt_k(const float* __restrict__ dt_bias, const float* __restrict__ A_log)
{
    int idx = blockIdx.x * blockDim.x + threadIdx.x;
    if (idx >= MTOK * NHH) return;
    int h = idx % NHH;
    int tok = idx / NHH;
    float x = g_zx[(size_t)tok * DPROJ + DIN + CONV_DIM + h] + dt_bias[h];
    float dt = (x > 20.f) ? x : log1pf(expf(x));
    g_dt[idx] = dt;
    g_dA[idx] = expf(-expf(A_log[h]) * dt);
}

// ---------------- sequential selective scan (register-prefetch pipelined) ----------------
__global__ void scan_k(const float* __restrict__ D_param)
{
    int b = blockIdx.x >> 5;
    int h = blockIdx.x & 31;
    int tid = threadIdx.x;
    int p = tid >> 3;
    int n0 = (tid & 7) * 8;
    float hs[8] = {};
    float Dv = D_param[h];

    const float* xrow = g_xbc + (size_t)(b * LL) * CONV_DIM;
    int tok0 = b * LL;

    float dA_c = g_dA[tok0*NHH + h];
    float dt_c = g_dt[tok0*NHH + h];
    float xp_c = xrow[h*HD + p];
    float4 B1c = *(const float4*)(xrow + DIN + n0);
    float4 B2c = *(const float4*)(xrow + DIN + n0 + 4);
    float4 C1c = *(const float4*)(xrow + DIN + DS + n0);
    float4 C2c = *(const float4*)(xrow + DIN + DS + n0 + 4);

    for (int t = 0; t < LL; t++) {
        float dA_n = 0.f, dt_n = 0.f, xp_n = 0.f;
        float4 B1n = {}, B2n = {}, C1n = {}, C2n = {};
        const float* xn = xrow + CONV_DIM;
        if (t + 1 < LL) {
            int tokn = tok0 + t + 1;
            dA_n = g_dA[tokn*NHH + h];
            dt_n = g_dt[tokn*NHH + h];
            xp_n = xn[h*HD + p];
            B1n = *(const float4*)(xn + DIN + n0);
            B2n = *(const float4*)(xn + DIN + n0 + 4);
            C1n = *(const float4*)(xn + DIN + DS + n0);
            C2n = *(const float4*)(xn + DIN + DS + n0 + 4);
        }

        float dtx = dt_c * xp_c;
        float Bv[8] = {B1c.x,B1c.y,B1c.z,B1c.w,B2c.x,B2c.y,B2c.z,B2c.w};
        float Cv[8] = {C1c.x,C1c.y,C1c.z,C1c.w,C2c.x,C2c.y,C2c.z,C2c.w};
        float part = 0.f;
        #pragma unroll
        for (int i = 0; i < 8; i++) {
            hs[i] = fmaf(dA_c, hs[i], dtx * Bv[i]);
            part  = fmaf(hs[i], Cv[i], part);
        }
        part += __shfl_down_sync(0xffffffffu, part, 4);
        part += __shfl_down_sync(0xffffffffu, part, 2);
        part += __shfl_down_sync(0xffffffffu, part, 1);
        if ((tid & 7) == 0)
            g_y[(size_t)(tok0 + t) * DIN + h*HD + p] = part + Dv * xp_c;

        dA_c = dA_n; dt_c = dt_n; xp_c = xp_n;
        B1c = B1n; B2c = B2n; C1c = C1n; C2c = C2n;
        xrow = xn;
    }
}

// ---------------- gated RMSNorm -> yn fp16 hi/lo ----------------
__global__ void gatenorm_k(const float* __restrict__ norm_w)
{
    int tok = blockIdx.x;
    __shared__ float sv[DIN];
    __shared__ float red[256];
    const float* yrow = g_y  + (size_t)tok * DIN;
    const float* zrow = g_zx + (size_t)tok * DPROJ;
    float ss = 0.f;
    for (int c = threadIdx.x; c < DIN; c += 256) {
        float z = zrow[c];
        float v = yrow[c] * (z / (1.f + expf(-z)));
        sv[c] = v;
        ss += v * v;
    }
    red[threadIdx.x] = ss; __syncthreads();
    for (int s = 128; s > 0; s >>= 1) {
        if (threadIdx.x < s) red[threadIdx.x] += red[threadIdx.x + s];
        __syncthreads();
    }
    float scale = rsqrtf(red[0] / DIN + EPSV);
    for (int c = threadIdx.x; c < DIN; c += 256) {
        float v = sv[c] * scale * norm_w[c];
        __half hh = __float2half(v);
        g_yn_h[(size_t)tok * DIN + c] = hh;
        g_yn_l[(size_t)tok * DIN + c] = __float2half(v - __half2float(hh));
    }
}

// ---------------- plain RMSNorm over DM -> hn fp16 hi/lo ----------------
__global__ void rmsnorm_k(const float* __restrict__ x, const float* __restrict__ w)
{
    int tok = blockIdx.x;
    __shared__ float sv[DM];
    __shared__ float red[256];
    const float* xr = x + (size_t)tok * DM;
    float ss = 0.f;
    for (int c = threadIdx.x; c < DM; c += 256) {
        float v = xr[c];
        sv[c] = v;
        ss += v * v;
    }
    red[threadIdx.x] = ss; __syncthreads();
    for (int s = 128; s > 0; s >>= 1) {
        if (threadIdx.x < s) red[threadIdx.x] += red[threadIdx.x + s];
        __syncthreads();
    }
    float scale = rsqrtf(red[0] / DM + EPSV);
    for (int c = threadIdx.x; c < DM; c += 256) {
        float v = sv[c] * scale * w[c];
        __half hh = __float2half(v);
        g_hn_h[(size_t)tok * DM + c] = hh;
        g_hn_l[(size_t)tok * DM + c] = __float2half(v - __half2float(hh));
    }
}

// ---------------- launch ----------------
extern "C" void kernel_launch(void* const* d_in, const int* in_sizes, int n_in,
                              void* d_out, int out_size)
{
    const float* x       = (const float*)d_in[0];
    const float* W_in    = (const float*)d_in[1];
    const float* conv_w  = (const float*)d_in[2];
    const float* conv_b  = (const float*)d_in[3];
    const float* dt_bias = (const float*)d_in[4];
    const float* A_log   = (const float*)d_in[5];
    const float* D_param = (const float*)d_in[6];
    const float* norm_w  = (const float*)d_in[7];
    const float* W_out   = (const float*)d_in[8];
    const float* rms_w   = (const float*)d_in[9];
    const float* mlp_w1  = (const float*)d_in[10];
    const float* mlp_b1  = (const float*)d_in[11];
    const float* mlp_w2  = (const float*)d_in[12];
    const float* mlp_b2  = (const float*)d_in[13];
    float* out           = (float*)d_out;
    (void)in_sizes; (void)n_in; (void)out_size;

    float *p_zx, *p_h;
    __half *p_xs_h, *p_xs_l, *p_yn_h, *p_yn_l, *p_hn_h, *p_hn_l, *p_act_h, *p_act_l;
    __half *p_win, *p_wout, *p_w1, *p_w2;
    cudaGetSymbolAddress((void**)&p_zx, g_zx);
    cudaGetSymbolAddress((void**)&p_h, g_h);
    cudaGetSymbolAddress((void**)&p_xs_h, g_xs_h);   cudaGetSymbolAddress((void**)&p_xs_l, g_xs_l);
    cudaGetSymbolAddress((void**)&p_yn_h, g_yn_h);   cudaGetSymbolAddress((void**)&p_yn_l, g_yn_l);
    cudaGetSymbolAddress((void**)&p_hn_h, g_hn_h);   cudaGetSymbolAddress((void**)&p_hn_l, g_hn_l);
    cudaGetSymbolAddress((void**)&p_act_h, g_act_h); cudaGetSymbolAddress((void**)&p_act_l, g_act_l);
    cudaGetSymbolAddress((void**)&p_win, g_win);
    cudaGetSymbolAddress((void**)&p_wout, g_wout);
    cudaGetSymbolAddress((void**)&p_w1, g_w1);
    cudaGetSymbolAddress((void**)&p_w2, g_w2);

    cudaFuncSetAttribute(gemm_mma<0,0,0,0>, cudaFuncAttributeMaxDynamicSharedMemorySize, GEMM_SMEM);
    cudaFuncSetAttribute(gemm_mma<0,0,1,0>, cudaFuncAttributeMaxDynamicSharedMemorySize, GEMM_SMEM);
    cudaFuncSetAttribute(gemm_mma<1,1,0,1>, cudaFuncAttributeMaxDynamicSharedMemorySize, GEMM_SMEM);
    cudaFuncSetAttribute(gemm_mma<1,0,1,0>, cudaFuncAttributeMaxDynamicSharedMemorySize, GEMM_SMEM);

    dim3 blk(256);

    // weight prep needed before their GEMMs (gemm1 placed 5th for ncu capture slot)
    split_k<<<(MTOK*DM + 255)/256, blk>>>(x, p_xs_h, p_xs_l, MTOK*DM);           // 1
    trconv_k<<<dim3(DPROJ_PAD/32, DM/32),  blk>>>(W_in,  p_win,  DM,   DPROJ, DPROJ_PAD); // 2
    trconv_k<<<dim3(DM/32,        DIN/32), blk>>>(W_out, p_wout, DIN,  DM,    DM);        // 3
    trconv_k<<<dim3(MLPI/32,      DM/32),  blk>>>(mlp_w1, p_w1,  DM,   MLPI,  MLPI);      // 4

    // 5. in-projection: zx = x @ W_in
    gemm_mma<0,0,0,0><<<dim3(DPROJ_PAD/NT, MTOK/MT), 512, GEMM_SMEM>>>(
        p_xs_h, p_xs_l, p_win, nullptr, nullptr, p_zx, nullptr, nullptr,
        MTOK, DPROJ, DM);
    // 6. conv + silu
    conv_k<<<(MTOK*CONV_DIM + 255)/256, blk>>>(conv_w, conv_b);
    // 7. dt / dA
    dt_k<<<(MTOK*NHH + 255)/256, blk>>>(dt_bias, A_log);
    // 8. scan
    scan_k<<<BB*NHH, 512>>>(D_param);
    // 9. remaining weight prep (independent of mamba chain)
    trconv_k<<<dim3(DM/32, MLPI/32), blk>>>(mlp_w2, p_w2, MLPI, DM, DM);
    // 10. gate + rmsnorm -> yn (split)
    gatenorm_k<<<MTOK, blk>>>(norm_w);
    // 11. h = x + yn @ W_out
    gemm_mma<0,0,1,0><<<dim3(DM/NT, MTOK/MT), 512, GEMM_SMEM>>>(
        p_yn_h, p_yn_l, p_wout, nullptr, x, p_h, nullptr, nullptr,
        MTOK, DM, DIN);
    // 12. hn = rmsnorm(h) (split)
    rmsnorm_k<<<MTOK, blk>>>(p_h, rms_w);
    // 13. act = silu(hn @ mlp_w1 + b1) (split)
    gemm_mma<1,1,0,1><<<dim3(MLPI/NT, MTOK/MT), 512, GEMM_SMEM>>>(
        p_hn_h, p_hn_l, p_w1, mlp_b1, nullptr, nullptr, p_act_h, p_act_l,
        MTOK, MLPI, DM);
    // 14. out = h + act @ mlp_w2 + b2
    gemm_mma<1,0,1,0><<<dim3(DM/NT, MTOK/MT), 512, GEMM_SMEM>>>(
        p_act_h, p_act_l, p_w2, mlp_b2, p_h, out, nullptr, nullptr,
        MTOK, DM, MLPI);
}

// round 6
// speedup vs baseline: 2.9725x; 1.1885x over previous
#include <cuda_runtime.h>
#include <cuda_fp16.h>
#include <math.h>
#include <stddef.h>
#include <stdint.h>

// ---------------- problem constants ----------------
#define BB 2
#define LL 2048
#define DM 1024
#define DIN 2048
#define NHH 32
#define HD 64
#define DS 64
#define DCONVK 4
#define CONV_DIM (DIN + 2*DS)        // 2176
#define DPROJ (2*DIN + 2*DS + NHH)   // 4256
#define DPROJ_PAD 4352               // multiple of 128
#define MLPI 4096
#define MTOK (BB*LL)                 // 4096
#define EPSV 1e-5f
#define NCH 16                       // scan chunks per sequence
#define CL  (LL/NCH)                 // 128 tokens per chunk

// ---------------- scratch (device globals) ----------------
__device__ float g_zx [MTOK*(size_t)DPROJ];
__device__ float g_xbc[MTOK*(size_t)CONV_DIM];
__device__ float g_dt [MTOK*NHH];
__device__ float g_dA [MTOK*NHH];
__device__ float g_cumdA[MTOK*NHH];
__device__ float g_y  [MTOK*(size_t)DIN];
__device__ float g_h  [MTOK*(size_t)DM];
__device__ float g_S  [BB*NHH*(size_t)NCH*HD*DS];   // per-chunk local final states
__device__ float g_Hi [BB*NHH*(size_t)NCH*HD*DS];   // per-chunk initial states

__device__ __half g_xs_h [MTOK*(size_t)DM],   g_xs_l [MTOK*(size_t)DM];
__device__ __half g_yn_h [MTOK*(size_t)DIN],  g_yn_l [MTOK*(size_t)DIN];
__device__ __half g_hn_h [MTOK*(size_t)DM],   g_hn_l [MTOK*(size_t)DM];
__device__ __half g_act_h[MTOK*(size_t)MLPI], g_act_l[MTOK*(size_t)MLPI];

__device__ __half g_win [DPROJ_PAD*(size_t)DM];
__device__ __half g_wout[DM*(size_t)DIN];
__device__ __half g_w1  [MLPI*(size_t)DM];
__device__ __half g_w2  [DM*(size_t)MLPI];

// ---------------- small asm helpers (baseline PTX, sm_80+) ----------------
__device__ __forceinline__ uint32_t smem_u32(const void* p) {
    uint32_t a;
    asm("{ .reg .u64 t; cvta.to.shared.u64 t, %1; cvt.u32.u64 %0, t; }" : "=r"(a) : "l"(p));
    return a;
}
__device__ __forceinline__ void cp_async16(uint32_t dst, const void* src) {
    asm volatile("cp.async.ca.shared.global [%0], [%1], 16;" :: "r"(dst), "l"(src) : "memory");
}
__device__ __forceinline__ void cp_commit() {
    asm volatile("cp.async.commit_group;" ::: "memory");
}
template<int N> __device__ __forceinline__ void cp_wait() {
    asm volatile("cp.async.wait_group %0;" :: "n"(N) : "memory");
}
__device__ __forceinline__ void ldsm4(uint32_t* r, uint32_t addr) {
    asm volatile("ldmatrix.sync.aligned.m8n8.x4.shared.b16 {%0,%1,%2,%3}, [%4];"
                 : "=r"(r[0]), "=r"(r[1]), "=r"(r[2]), "=r"(r[3]) : "r"(addr));
}
__device__ __forceinline__ void ldsm2(uint32_t* r, uint32_t addr) {
    asm volatile("ldmatrix.sync.aligned.m8n8.x2.shared.b16 {%0,%1}, [%2];"
                 : "=r"(r[0]), "=r"(r[1]) : "r"(addr));
}
__device__ __forceinline__ void mma16816(float* c, const uint32_t* a, const uint32_t* b) {
    asm volatile(
        "mma.sync.aligned.m16n8k16.row.col.f32.f16.f16.f32 "
        "{%0,%1,%2,%3}, {%4,%5,%6,%7}, {%8,%9}, {%0,%1,%2,%3};"
        : "+f"(c[0]), "+f"(c[1]), "+f"(c[2]), "+f"(c[3])
        : "r"(a[0]), "r"(a[1]), "r"(a[2]), "r"(a[3]), "r"(b[0]), "r"(b[1]));
}

// ---------------- fp16 HMMA 2-term split GEMM (unchanged from R5) ----------------
#define MT 256
#define NT 128
#define KC 64
#define STG_BYTES 81920
#define GEMM_SMEM (2*STG_BYTES)

template<int HAS_BIAS, int DO_SILU, int HAS_RES, int OUT_SPLIT>
__global__ void __launch_bounds__(512)
gemm_mma(const __half* __restrict__ Ah, const __half* __restrict__ Al,
         const __half* __restrict__ Bh,
         const float* __restrict__ bias, const float* __restrict__ res,
         float* __restrict__ Cf, __half* __restrict__ Chi, __half* __restrict__ Clo,
         int M, int N, int K)
{
    extern __shared__ char smem[];
    const uint32_t sbase = smem_u32(smem);
    const int tid = threadIdx.x;
    const int lane = tid & 31;
    const int wid = tid >> 5;
    const int row0 = blockIdx.y * MT;
    const int col0 = blockIdx.x * NT;
    const int wr0 = (wid & 3) * 64;
    const int wc0 = (wid >> 2) * 32;

    float c[4][4][4];
    #pragma unroll
    for (int m = 0; m < 4; m++)
        #pragma unroll
        for (int j = 0; j < 4; j++)
            #pragma unroll
            for (int e = 0; e < 4; e++) c[m][j][e] = 0.f;

    const int nch = K / KC;

    auto load_stage = [&](int kc) {
        const int koff = kc * KC;
        const uint32_t st = sbase + (kc & 1) * STG_BYTES;
        #pragma unroll
        for (int i = 0; i < 4; i++) {
            int ch = tid + i * 512;
            int r = ch >> 3, c16 = ch & 7;
            uint32_t soff = (uint32_t)(r * 128 + ((c16 * 16) ^ ((r & 7) << 4)));
            const size_t go = (size_t)(row0 + r) * K + koff + c16 * 8;
            cp_async16(st + soff,         Ah + go);
            cp_async16(st + 32768 + soff, Al + go);
        }
        #pragma unroll
        for (int i = 0; i < 2; i++) {
            int ch = tid + i * 512;
            int r = ch >> 3, c16 = ch & 7;
            uint32_t soff = (uint32_t)(r * 128 + ((c16 * 16) ^ ((r & 7) << 4)));
            cp_async16(st + 65536 + soff, Bh + (size_t)(col0 + r) * K + koff + c16 * 8);
        }
        cp_commit();
    };

    load_stage(0);

    for (int kc = 0; kc < nch; kc++) {
        if (kc + 1 < nch) { load_stage(kc + 1); cp_wait<1>(); }
        else              { cp_wait<0>(); }
        __syncthreads();

        const uint32_t st = sbase + (kc & 1) * STG_BYTES;

        #pragma unroll
        for (int ks = 0; ks < 4; ks++) {
            uint32_t a[4][4], b[4][2];
            #pragma unroll
            for (int j = 0; j < 4; j++) {
                int l = lane & 15;
                int r = wc0 + j * 8 + (l & 7);
                int cb = (ks * 2 + (l >> 3)) * 16;
                ldsm2(b[j], st + 65536 + (uint32_t)(r * 128 + (cb ^ ((r & 7) << 4))));
            }
            #pragma unroll
            for (int m = 0; m < 4; m++) {
                int r = wr0 + m * 16 + (lane & 15);
                int cb = (ks * 2 + (lane >> 4)) * 16;
                ldsm4(a[m], st + r * 128 + (cb ^ ((r & 7) << 4)));
            }
            #pragma unroll
            for (int m = 0; m < 4; m++)
                #pragma unroll
                for (int j = 0; j < 4; j++)
                    mma16816(c[m][j], a[m], b[j]);
            #pragma unroll
            for (int m = 0; m < 4; m++) {
                int r = wr0 + m * 16 + (lane & 15);
                int cb = (ks * 2 + (lane >> 4)) * 16;
                ldsm4(a[m], st + 32768 + r * 128 + (cb ^ ((r & 7) << 4)));
            }
            #pragma unroll
            for (int m = 0; m < 4; m++)
                #pragma unroll
                for (int j = 0; j < 4; j++)
                    mma16816(c[m][j], a[m], b[j]);
        }
        __syncthreads();
    }

    #pragma unroll
    for (int m = 0; m < 4; m++) {
        const int r_ = row0 + wr0 + m * 16 + (lane >> 2);
        #pragma unroll
        for (int j = 0; j < 4; j++) {
            const int c_ = col0 + wc0 + j * 8 + 2 * (lane & 3);
            #pragma unroll
            for (int e = 0; e < 4; e++) {
                const int rr = r_ + (e >> 1) * 8;
                const int cc = c_ + (e & 1);
                if (cc < N) {
                    float v = c[m][j][e];
                    if (HAS_BIAS) v += bias[cc];
                    if (DO_SILU)  v = v / (1.f + expf(-v));
                    if (HAS_RES)  v += res[(size_t)rr * N + cc];
                    if (OUT_SPLIT) {
                        __half hh = __float2half(v);
                        Chi[(size_t)rr * N + cc] = hh;
                        Clo[(size_t)rr * N + cc] = __float2half(v - __half2float(hh));
                    } else {
                        Cf[(size_t)rr * N + cc] = v;
                    }
                }
            }
        }
    }
}

// ---------------- split fp32 -> fp16 hi/lo ----------------
__global__ void split_k(const float* __restrict__ x, __half* __restrict__ h,
                        __half* __restrict__ l, int n)
{
    int i = blockIdx.x * blockDim.x + threadIdx.x;
    if (i >= n) return;
    float v = x[i];
    __half hh = __float2half(v);
    h[i] = hh;
    l[i] = __float2half(v - __half2float(hh));
}

// ---------------- transpose + convert: W[K][N] fp32 -> T[Npad][K] fp16 ----------------
__global__ void trconv_k(const float* __restrict__ W, __half* __restrict__ Th,
                         int K, int N, int Npad)
{
    __shared__ float t[32][33];
    int kb = blockIdx.y * 32, nb = blockIdx.x * 32;
    int x = threadIdx.x & 31, y = threadIdx.x >> 5;
    #pragma unroll
    for (int i = y; i < 32; i += 8) {
        int kk = kb + i, nn = nb + x;
        t[i][x] = (kk < K && nn < N) ? W[(size_t)kk * N + nn] : 0.f;
    }
    __syncthreads();
    #pragma unroll
    for (int i = y; i < 32; i += 8) {
        int nn = nb + i, kk = kb + x;
        if (nn < Npad && kk < K)
            Th[(size_t)nn * K + kk] = __float2half(t[x][i]);
    }
}

// ---------------- depthwise causal conv (k=4) + bias + silu ----------------
__global__ void conv_k(const float* __restrict__ conv_w, const float* __restrict__ conv_b)
{
    int idx = blockIdx.x * blockDim.x + threadIdx.x;
    if (idx >= MTOK * CONV_DIM) return;
    int c = idx % CONV_DIM;
    int tok = idx / CONV_DIM;
    int t = tok % LL;
    long long base = (long long)tok * DPROJ + DIN + c;
    float acc = conv_b[c];
    #pragma unroll
    for (int k = 0; k < DCONVK; k++) {
        int tt = t - (DCONVK - 1) + k;
        if (tt >= 0)
            acc = fmaf(g_zx[base + (long long)(k - (DCONVK - 1)) * DPROJ], conv_w[c*DCONVK + k], acc);
    }
    g_xbc[idx] = acc / (1.f + expf(-acc));
}

// ---------------- dt / dA ----------------
__global__ void dt_k(const float* __restrict__ dt_bias, const float* __restrict__ A_log)
{
    int idx = blockIdx.x * blockDim.x + threadIdx.x;
    if (idx >= MTOK * NHH) return;
    int h = idx % NHH;
    int tok = idx / NHH;
    float x = g_zx[(size_t)tok * DPROJ + DIN + CONV_DIM + h] + dt_bias[h];
    float dt = (x > 20.f) ? x : log1pf(expf(x));
    g_dt[idx] = dt;
    g_dA[idx] = expf(-expf(A_log[h]) * dt);
}

// ---------------- Phase A: per-chunk local scan (h0 = 0) ----------------
// grid (NCH, BB*NHH), 512 threads: thread owns p = tid>>3, n-slice (tid&7)*8.
// Writes local y (+D*xs), per-token cumdA, final local state S.
__global__ void scan_local_k(const float* __restrict__ D_param)
{
    int chunk = blockIdx.x;
    int bh = blockIdx.y;
    int b = bh >> 5;
    int h = bh & 31;
    int tid = threadIdx.x;
    int p = tid >> 3;
    int n0 = (tid & 7) * 8;
    float hs[8] = {};
    float Dv = D_param[h];
    float cum = 1.f;

    int tok0 = b * LL + chunk * CL;
    const float* xrow = g_xbc + (size_t)tok0 * CONV_DIM;

    float dA_c = g_dA[tok0*NHH + h];
    float dt_c = g_dt[tok0*NHH + h];
    float xp_c = xrow[h*HD + p];
    float4 B1c = *(const float4*)(xrow + DIN + n0);
    float4 B2c = *(const float4*)(xrow + DIN + n0 + 4);
    float4 C1c = *(const float4*)(xrow + DIN + DS + n0);
    float4 C2c = *(const float4*)(xrow + DIN + DS + n0 + 4);

    for (int t = 0; t < CL; t++) {
        float dA_n = 0.f, dt_n = 0.f, xp_n = 0.f;
        float4 B1n = {}, B2n = {}, C1n = {}, C2n = {};
        const float* xn = xrow + CONV_DIM;
        if (t + 1 < CL) {
            int tokn = tok0 + t + 1;
            dA_n = g_dA[tokn*NHH + h];
            dt_n = g_dt[tokn*NHH + h];
            xp_n = xn[h*HD + p];
            B1n = *(const float4*)(xn + DIN + n0);
            B2n = *(const float4*)(xn + DIN + n0 + 4);
            C1n = *(const float4*)(xn + DIN + DS + n0);
            C2n = *(const float4*)(xn + DIN + DS + n0 + 4);
        }

        cum *= dA_c;
        float dtx = dt_c * xp_c;
        float Bv[8] = {B1c.x,B1c.y,B1c.z,B1c.w,B2c.x,B2c.y,B2c.z,B2c.w};
        float Cv[8] = {C1c.x,C1c.y,C1c.z,C1c.w,C2c.x,C2c.y,C2c.z,C2c.w};
        float part = 0.f;
        #pragma unroll
        for (int i = 0; i < 8; i++) {
            hs[i] = fmaf(dA_c, hs[i], dtx * Bv[i]);
            part  = fmaf(hs[i], Cv[i], part);
        }
        part += __shfl_down_sync(0xffffffffu, part, 4);
        part += __shfl_down_sync(0xffffffffu, part, 2);
        part += __shfl_down_sync(0xffffffffu, part, 1);
        int tok = tok0 + t;
        if ((tid & 7) == 0)
            g_y[(size_t)tok * DIN + h*HD + p] = part + Dv * xp_c;
        if (tid == 0)
            g_cumdA[tok*NHH + h] = cum;

        dA_c = dA_n; dt_c = dt_n; xp_c = xp_n;
        B1c = B1n; B2c = B2n; C1c = C1n; C2c = C2n;
        xrow = xn;
    }

    // store local final state
    float* Sp = g_S + ((size_t)bh * NCH + chunk) * (HD*DS) + p * DS + n0;
    #pragma unroll
    for (int i = 0; i < 8; i++) Sp[i] = hs[i];
}

// ---------------- Phase B: combine chunk states serially (tiny) ----------------
// grid 64 (bh), 512 threads; H_init[c+1] = P_c * H_init[c] + S_c.
__global__ void scan_combine_k()
{
    int bh = blockIdx.x;
    int b = bh >> 5;
    int h = bh & 31;
    int tid = threadIdx.x;
    int p = tid >> 3;
    int n0 = (tid & 7) * 8;
    float H[8] = {};

    for (int c = 0; c < NCH; c++) {
        float* Hp = g_Hi + ((size_t)bh * NCH + c) * (HD*DS) + p * DS + n0;
        #pragma unroll
        for (int i = 0; i < 8; i++) Hp[i] = H[i];
        if (c + 1 < NCH) {
            int lastTok = b * LL + c * CL + (CL - 1);
            float Pc = g_cumdA[lastTok*NHH + h];
            const float* Sp = g_S + ((size_t)bh * NCH + c) * (HD*DS) + p * DS + n0;
            #pragma unroll
            for (int i = 0; i < 8; i++) H[i] = fmaf(Pc, H[i], Sp[i]);
        }
    }
}

// ---------------- Phase C: cross-chunk correction ----------------
// y_t += cumdA_t * (C_t . H_init[chunk]); skip chunk 0 (H=0).
__global__ void scan_correct_k()
{
    int chunk = blockIdx.x + 1;          // 1..NCH-1
    int bh = blockIdx.y;
    int b = bh >> 5;
    int h = bh & 31;
    int tid = threadIdx.x;
    int p = tid >> 3;
    int n0 = (tid & 7) * 8;

    float H[8];
    const float* Hp = g_Hi + ((size_t)bh * NCH + chunk) * (HD*DS) + p * DS + n0;
    #pragma unroll
    for (int i = 0; i < 8; i++) H[i] = Hp[i];

    int tok0 = b * LL + chunk * CL;
    const float* xrow = g_xbc + (size_t)tok0 * CONV_DIM;

    for (int t = 0; t < CL; t++) {
        int tok = tok0 + t;
        float4 C1 = *(const float4*)(xrow + DIN + DS + n0);
        float4 C2 = *(const float4*)(xrow + DIN + DS + n0 + 4);
        float cum = g_cumdA[tok*NHH + h];
        float Cv[8] = {C1.x,C1.y,C1.z,C1.w,C2.x,C2.y,C2.z,C2.w};
        float part = 0.f;
        #pragma unroll
        for (int i = 0; i < 8; i++) part = fmaf(H[i], Cv[i], part);
        part += __shfl_down_sync(0xffffffffu, part, 4);
        part += __shfl_down_sync(0xffffffffu, part, 2);
        part += __shfl_down_sync(0xffffffffu, part, 1);
        if ((tid & 7) == 0)
            g_y[(size_t)tok * DIN + h*HD + p] += cum * part;
        xrow += CONV_DIM;
    }
}

// ---------------- gated RMSNorm -> yn fp16 hi/lo ----------------
__global__ void gatenorm_k(const float* __restrict__ norm_w)
{
    int tok = blockIdx.x;
    __shared__ float sv[DIN];
    __shared__ float red[256];
    const float* yrow = g_y  + (size_t)tok * DIN;
    const float* zrow = g_zx + (size_t)tok * DPROJ;
    float ss = 0.f;
    for (int c = threadIdx.x; c < DIN; c += 256) {
        float z = zrow[c];
        float v = yrow[c] * (z / (1.f + expf(-z)));
        sv[c] = v;
        ss += v * v;
    }
    red[threadIdx.x] = ss; __syncthreads();
    for (int s = 128; s > 0; s >>= 1) {
        if (threadIdx.x < s) red[threadIdx.x] += red[threadIdx.x + s];
        __syncthreads();
    }
    float scale = rsqrtf(red[0] / DIN + EPSV);
    for (int c = threadIdx.x; c < DIN; c += 256) {
        float v = sv[c] * scale * norm_w[c];
        __half hh = __float2half(v);
        g_yn_h[(size_t)tok * DIN + c] = hh;
        g_yn_l[(size_t)tok * DIN + c] = __float2half(v - __half2float(hh));
    }
}

// ---------------- plain RMSNorm over DM -> hn fp16 hi/lo ----------------
__global__ void rmsnorm_k(const float* __restrict__ x, const float* __restrict__ w)
{
    int tok = blockIdx.x;
    __shared__ float sv[DM];
    __shared__ float red[256];
    const float* xr = x + (size_t)tok * DM;
    float ss = 0.f;
    for (int c = threadIdx.x; c < DM; c += 256) {
        float v = xr[c];
        sv[c] = v;
        ss += v * v;
    }
    red[threadIdx.x] = ss; __syncthreads();
    for (int s = 128; s > 0; s >>= 1) {
        if (threadIdx.x < s) red[threadIdx.x] += red[threadIdx.x + s];
        __syncthreads();
    }
    float scale = rsqrtf(red[0] / DM + EPSV);
    for (int c = threadIdx.x; c < DM; c += 256) {
        float v = sv[c] * scale * w[c];
        __half hh = __float2half(v);
        g_hn_h[(size_t)tok * DM + c] = hh;
        g_hn_l[(size_t)tok * DM + c] = __float2half(v - __half2float(hh));
    }
}

// ---------------- launch ----------------
extern "C" void kernel_launch(void* const* d_in, const int* in_sizes, int n_in,
                              void* d_out, int out_size)
{
    const float* x       = (const float*)d_in[0];
    const float* W_in    = (const float*)d_in[1];
    const float* conv_w  = (const float*)d_in[2];
    const float* conv_b  = (const float*)d_in[3];
    const float* dt_bias = (const float*)d_in[4];
    const float* A_log   = (const float*)d_in[5];
    const float* D_param = (const float*)d_in[6];
    const float* norm_w  = (const float*)d_in[7];
    const float* W_out   = (const float*)d_in[8];
    const float* rms_w   = (const float*)d_in[9];
    const float* mlp_w1  = (const float*)d_in[10];
    const float* mlp_b1  = (const float*)d_in[11];
    const float* mlp_w2  = (const float*)d_in[12];
    const float* mlp_b2  = (const float*)d_in[13];
    float* out           = (float*)d_out;
    (void)in_sizes; (void)n_in; (void)out_size;

    float *p_zx, *p_h;
    __half *p_xs_h, *p_xs_l, *p_yn_h, *p_yn_l, *p_hn_h, *p_hn_l, *p_act_h, *p_act_l;
    __half *p_win, *p_wout, *p_w1, *p_w2;
    cudaGetSymbolAddress((void**)&p_zx, g_zx);
    cudaGetSymbolAddress((void**)&p_h, g_h);
    cudaGetSymbolAddress((void**)&p_xs_h, g_xs_h);   cudaGetSymbolAddress((void**)&p_xs_l, g_xs_l);
    cudaGetSymbolAddress((void**)&p_yn_h, g_yn_h);   cudaGetSymbolAddress((void**)&p_yn_l, g_yn_l);
    cudaGetSymbolAddress((void**)&p_hn_h, g_hn_h);   cudaGetSymbolAddress((void**)&p_hn_l, g_hn_l);
    cudaGetSymbolAddress((void**)&p_act_h, g_act_h); cudaGetSymbolAddress((void**)&p_act_l, g_act_l);
    cudaGetSymbolAddress((void**)&p_win, g_win);
    cudaGetSymbolAddress((void**)&p_wout, g_wout);
    cudaGetSymbolAddress((void**)&p_w1, g_w1);
    cudaGetSymbolAddress((void**)&p_w2, g_w2);

    cudaFuncSetAttribute(gemm_mma<0,0,0,0>, cudaFuncAttributeMaxDynamicSharedMemorySize, GEMM_SMEM);
    cudaFuncSetAttribute(gemm_mma<0,0,1,0>, cudaFuncAttributeMaxDynamicSharedMemorySize, GEMM_SMEM);
    cudaFuncSetAttribute(gemm_mma<1,1,0,1>, cudaFuncAttributeMaxDynamicSharedMemorySize, GEMM_SMEM);
    cudaFuncSetAttribute(gemm_mma<1,0,1,0>, cudaFuncAttributeMaxDynamicSharedMemorySize, GEMM_SMEM);

    dim3 blk(256);

    split_k<<<(MTOK*DM + 255)/256, blk>>>(x, p_xs_h, p_xs_l, MTOK*DM);
    trconv_k<<<dim3(DPROJ_PAD/32, DM/32),  blk>>>(W_in,  p_win,  DM,   DPROJ, DPROJ_PAD);
    trconv_k<<<dim3(DM/32,        DIN/32), blk>>>(W_out, p_wout, DIN,  DM,    DM);
    trconv_k<<<dim3(MLPI/32,      DM/32),  blk>>>(mlp_w1, p_w1,  DM,   MLPI,  MLPI);

    // in-projection: zx = x @ W_in
    gemm_mma<0,0,0,0><<<dim3(DPROJ_PAD/NT, MTOK/MT), 512, GEMM_SMEM>>>(
        p_xs_h, p_xs_l, p_win, nullptr, nullptr, p_zx, nullptr, nullptr,
        MTOK, DPROJ, DM);
    // conv + silu
    conv_k<<<(MTOK*CONV_DIM + 255)/256, blk>>>(conv_w, conv_b);
    // dt / dA
    dt_k<<<(MTOK*NHH + 255)/256, blk>>>(dt_bias, A_log);
    // chunked scan: local -> combine -> correct
    scan_local_k<<<dim3(NCH, BB*NHH), 512>>>(D_param);
    scan_combine_k<<<BB*NHH, 512>>>();
    scan_correct_k<<<dim3(NCH-1, BB*NHH), 512>>>();
    // remaining weight prep (overlaps dependency chain)
    trconv_k<<<dim3(DM/32, MLPI/32), blk>>>(mlp_w2, p_w2, MLPI, DM, DM);
    // gate + rmsnorm -> yn (split)
    gatenorm_k<<<MTOK, blk>>>(norm_w);
    // h = x + yn @ W_out
    gemm_mma<0,0,1,0><<<dim3(DM/NT, MTOK/MT), 512, GEMM_SMEM>>>(
        p_yn_h, p_yn_l, p_wout, nullptr, x, p_h, nullptr, nullptr,
        MTOK, DM, DIN);
    // hn = rmsnorm(h) (split)
    rmsnorm_k<<<MTOK, blk>>>(p_h, rms_w);
    // act = silu(hn @ mlp_w1 + b1) (split)
    gemm_mma<1,1,0,1><<<dim3(MLPI/NT, MTOK/MT), 512, GEMM_SMEM>>>(
        p_hn_h, p_hn_l, p_w1, mlp_b1, nullptr, nullptr, p_act_h, p_act_l,
        MTOK, MLPI, DM);
    // out = h + act @ mlp_w2 + b2
    gemm_mma<1,0,1,0><<<dim3(DM/NT, MTOK/MT), 512, GEMM_SMEM>>>(
        p_act_h, p_act_l, p_w2, mlp_b2, p_h, out, nullptr, nullptr,
        MTOK, DM, MLPI);
}